// round 12
// baseline (speedup 1.0000x reference)
#include <cuda_runtime.h>
#include <cuda_bf16.h>
#include <math.h>

// ---------------------------------------------------------------------------
// Problem constants
// ---------------------------------------------------------------------------
#define N_NODES   10000
#define N_EDGES   250000
#define FF        32
#define HIDDEN    64
#define NPATHS    11
#define FEAT      288
#define NRAD      352

#define EPB       64          // edges per block
#define BLK       256         // threads per block (8 warps, 8 edges/warp)
#define M_PITCH   144         // padded pitch for M[e][elem]; path blocks 16B-aligned
#define Y_PITCH   16          // ysm pitch: 8 harmonics, [8]=1, [9..15]=0

#define RTAB_N    8192        // intervals over d in [0,4]
#define RTAB_ROWS (RTAB_N + 1)

// PATHS = [(0,0,0),(0,1,1),(0,2,2),(1,0,1),(1,1,0),(1,1,2),
//          (1,2,1),(2,0,2),(2,1,1),(2,2,0),(2,2,2)]
__constant__ int c_PI[NPATHS]  = {0,0,0,1,1,1,1,2,2,2,2};
__constant__ int c_PJ[NPATHS]  = {0,1,2,0,1,1,2,0,1,2,2};
__constant__ int c_PK[NPATHS]  = {0,1,2,1,0,2,1,2,1,0,2};
// dense element-offset of path p (sizes {1,3,5,9,3,15,9,25,15,5,25} -> 115)
__constant__ int c_OFF[NPATHS]  = {0,1,4,9,18,21,36,45,70,85,90};
// padded (16B-aligned) offsets within the 144-float per-edge M vector
__constant__ int c_OFFP[NPATHS] = {0,4,8,16,28,32,48,60,88,104,112};
// PATH_W[p]/sqrt(25)
__constant__ float c_PW[NPATHS] = {
    0.11547005383792515f, 0.17320508075688773f, 0.22360679774997896f,
    0.17320508075688773f, 0.11547005383792515f, 0.22360679774997896f,
    0.17320508075688773f, 0.22360679774997896f, 0.17320508075688773f,
    0.11547005383792515f, 0.22360679774997896f};

// Transposed, pre-scaled W3J: w3jT[idx][b] = W3J[p][a, b, c] * PW[p], rows
// padded to 5 (b >= 2j+1 -> 0), idx 115..127 all-zero.
__device__ float g_w3jT[128 * 5];
// Interleaved radial*cutoff table: g_rtab2[i*NRAD+r] = {rad(d_i)[r], rad(d_{i+1})[r]}
__device__ float2 g_rtab2[RTAB_N * NRAD];        // 23 MB static scratch
// Channel-major repacked node features
__device__ float g_nodesT[N_NODES * FEAT];       // 11.5 MB static scratch
// Channel-major output accumulator (transposed back at the end)
__device__ __align__(16) float g_outT[N_NODES * FEAT];

// ---------------------------------------------------------------------------
// Setup kernel: zero g_outT + repack nodes + compute w3jT (sparse scatter).
// ---------------------------------------------------------------------------
__device__ __forceinline__ float ffact(int n) {
    float r = 1.0f;
    for (int i = 2; i <= n; ++i) r *= (float)i;
    return r;
}

__device__ float su2_cg_f(int j1, int j2, int j3, int m1, int m2, int m3) {
    if (m1 + m2 != m3) return 0.0f;
    float pref = sqrtf((2.0f * j3 + 1.0f) * ffact(j1 + j2 - j3) * ffact(j1 - j2 + j3) *
                       ffact(-j1 + j2 + j3) / ffact(j1 + j2 + j3 + 1));
    pref *= sqrtf(ffact(j3 + m3) * ffact(j3 - m3) * ffact(j1 - m1) * ffact(j1 + m1) *
                  ffact(j2 - m2) * ffact(j2 + m2));
    float s = 0.0f;
    for (int k = 0; k <= j1 + j2 - j3; ++k) {
        int e1 = j1 + j2 - j3 - k, e2 = j1 - m1 - k, e3 = j2 + m2 - k;
        int e4 = j3 - j2 + m1 + k, e5 = j3 - j1 - m2 + k;
        if (e1 < 0 || e2 < 0 || e3 < 0 || e4 < 0 || e5 < 0) continue;
        float term = 1.0f / (ffact(k) * ffact(e1) * ffact(e2) * ffact(e3) *
                             ffact(e4) * ffact(e5));
        s += (k & 1) ? -term : term;
    }
    return pref * s;
}

// nonzeros of row r of q(l), including the (-1j)^l prefactor. Returns count (1 or 2).
__device__ __forceinline__ int qrow(int l, int r, int* col, float* re, float* im) {
    const float is2 = 0.70710678118654752440f;
    int m = r - l;
    int cnt;
    float a[2], b[2];
    if (m < 0) {
        col[0] = l - m; a[0] = is2;  b[0] = 0.f;
        col[1] = l + m; a[1] = 0.f;  b[1] = -is2;
        cnt = 2;
    } else if (m == 0) {
        col[0] = l; a[0] = 1.f; b[0] = 0.f;
        cnt = 1;
    } else {
        float sg = (m & 1) ? -1.f : 1.f;
        col[0] = l + m; a[0] = sg * is2; b[0] = 0.f;
        col[1] = l - m; a[1] = 0.f;      b[1] = sg * is2;
        cnt = 2;
    }
    #pragma unroll
    for (int q = 0; q < 2; ++q) {
        if (q >= cnt) break;
        float A = a[q], B = b[q];
        if (l == 1) { float tA = B, tB = -A; A = tA; B = tB; }   // *(-i)
        else if (l == 2) { A = -A; B = -B; }                     // *(-1)
        re[q] = A; im[q] = B;
    }
    return cnt;
}

#define SETUP_BLOCKS 2048

__global__ void __launch_bounds__(128) setup_kernel(const float* __restrict__ nodes)
{
    // grid-stride zero of the transposed accumulator (float4)
    {
        float4* o4 = (float4*)g_outT;
        float4 z = make_float4(0.f, 0.f, 0.f, 0.f);
        for (int i = blockIdx.x * blockDim.x + threadIdx.x; i < N_NODES * FEAT / 4;
             i += gridDim.x * blockDim.x)
            o4[i] = z;
    }
    // grid-stride node repack (channel-major)
    for (int idx = blockIdx.x * blockDim.x + threadIdx.x; idx < N_NODES * FEAT;
         idx += gridDim.x * blockDim.x) {
        int n = idx / FEAT, r = idx - n * FEAT;
        float v;
        if (r < 32) {
            v = nodes[n * FEAT + r];
        } else if (r < 128) {
            int a = (r - 32) >> 5, uu = (r - 32) & 31;
            v = nodes[n * FEAT + 32 + uu * 3 + a];
        } else {
            int a = (r - 128) >> 5, uu = (r - 128) & 31;
            v = nodes[n * FEAT + 128 + uu * 5 + a];
        }
        g_nodesT[idx] = v;
    }
    if (blockIdx.x >= NPATHS) return;

    int p = blockIdx.x, t = threadIdx.x;
    int l1 = c_PI[p], l2 = c_PJ[p], l3 = c_PK[p];
    int d1 = 2 * l1 + 1, d2 = 2 * l2 + 1, d3 = 2 * l3 + 1;
    int n = d1 * d2 * d3;
    __shared__ float C[125], Wre[125], Wim[125];
    __shared__ float sel[2];

    for (int idx = t; idx < n; idx += blockDim.x) {
        int i = idx / (d2 * d3), k = (idx / d3) % d2, m = idx % d3;
        C[idx] = su2_cg_f(l1, l2, l3, i - l1, k - l2, m - l3);
        Wre[idx] = 0.f; Wim[idx] = 0.f;
    }
    __syncthreads();

    // sparse scatter: each nonzero C entry contributes <=8 outputs
    for (int idx = t; idx < n; idx += blockDim.x) {
        float cc = C[idx];
        if (cc == 0.f) continue;
        int i = idx / (d2 * d3), k = (idx / d3) % d2, m = idx % d3;
        int   c1[2], c2[2], c3[2];
        float a1[2], b1[2], a2[2], b2[2], a3[2], b3[2];
        int n1 = qrow(l1, i, c1, a1, b1);
        int n2 = qrow(l2, k, c2, a2, b2);
        int n3 = qrow(l3, m, c3, a3, b3);
        for (int x = 0; x < n1; ++x)
            for (int y = 0; y < n2; ++y) {
                float pr = a1[x] * a2[y] - b1[x] * b2[y];
                float pi = a1[x] * b2[y] + b1[x] * a2[y];
                for (int z = 0; z < n3; ++z) {
                    float rr = pr * a3[z] + pi * b3[z];   // * conj(q3)
                    float ri = pi * a3[z] - pr * b3[z];
                    int o = (c1[x] * d2 + c2[y]) * d3 + c3[z];
                    atomicAdd(&Wre[o], cc * rr);
                    atomicAdd(&Wim[o], cc * ri);
                }
            }
    }
    __syncthreads();

    if (t == 0) {
        float nr = 0.0f, ni = 0.0f;
        for (int idx = 0; idx < n; ++idx) {
            nr += Wre[idx] * Wre[idx];
            ni += Wim[idx] * Wim[idx];
        }
        nr = sqrtf(nr); ni = sqrtf(ni);
        sel[0] = (nr >= ni) ? 1.0f : 0.0f;
        sel[1] = (nr >= ni) ? nr : ni;
    }
    __syncthreads();

    bool useRe = sel[0] > 0.5f;
    float scl = c_PW[p] / sel[1];
    const float* W = useRe ? Wre : Wim;

    // write transposed, pre-scaled rows for this path:
    //   w3jT[(off+r)*5 + b] = W[(a*d2+b)*d3 + c] * PW/norm  (b < d2, else 0)
    int off = c_OFF[p];
    int nr5 = d1 * d3 * 5;
    for (int rb = t; rb < nr5; rb += blockDim.x) {
        int r = rb / 5, b = rb - r * 5;
        int a = r / d3, c = r - a * d3;
        float v = (b < d2) ? W[(a * d2 + b) * d3 + c] * scl : 0.f;
        g_w3jT[(off + r) * 5 + b] = v;
    }
    if (p == 0)
        for (int z = t; z < 65; z += blockDim.x) g_w3jT[575 + z] = 0.f;
}

// ---------------------------------------------------------------------------
// Radial table build: 2 rows per 256-thread block; interleaved {row i, row i+1}.
// Table stores radial_raw(d) * poly_cutoff(d).
// ---------------------------------------------------------------------------
__global__ void __launch_bounds__(256) rtab_kernel(
    const float* __restrict__ w1, const float* __restrict__ b1,
    const float* __restrict__ w2, const float* __restrict__ b2)
{
    __shared__ float h[2][HIDDEN];
    __shared__ float cutf[2];
    int t = threadIdx.x;
    int i0 = blockIdx.x * 2;
    int sub = t >> 6, l64 = t & 63;

    if (sub < 2) {
        int i = i0 + sub;
        if (i < RTAB_ROWS) {
            float d = (float)i * (4.0f / (float)RTAB_N);
            float tt = d * 0.2f;                       // d / BESSEL_END
            float a = b1[l64];
            if (tt > 0.0f && tt < 1.0f) {
                float cc = 0.6324555320336759f / tt;   // sqrt(2/5)/t
                #pragma unroll
                for (int n = 1; n <= 8; ++n) {
                    float bv = cc * sinf((float)n * 3.14159265358979323846f * tt);
                    a = fmaf(bv, w1[(n - 1) * HIDDEN + l64], a);
                }
            }
            h[sub][l64] = a / (1.0f + __expf(-a));     // silu
            if (l64 == 0) {
                float cv = 0.f;
                if (d < 4.0f) {
                    float uu = d * 0.25f;
                    float u2 = uu * uu, u4 = u2 * u2, u5 = u4 * uu;
                    cv = 1.0f - 6.0f * u5 + 5.0f * u5 * uu;
                }
                cutf[sub] = cv;
            }
        }
    }
    __syncthreads();

    float* tab = reinterpret_cast<float*>(g_rtab2);
    #pragma unroll
    for (int k = 0; k < 3; ++k) {
        int o = k * 256 + t;
        if (o < 704) {
            int row = (o >= NRAD) ? 1 : 0;
            int r = o - row * NRAD;
            int i = i0 + row;
            if (i < RTAB_ROWS) {
                float s = b2[r];
                #pragma unroll 8
                for (int j = 0; j < HIDDEN; ++j) s = fmaf(h[row][j], w2[j * NRAD + r], s);
                s *= cutf[row];
                if (i < RTAB_N) tab[2 * (i * NRAD + r)] = s;            // .x of row i
                if (i > 0)      tab[2 * ((i - 1) * NRAD + r) + 1] = s;  // .y of row i-1
            }
        }
    }
}

// ---------------------------------------------------------------------------
// Final transpose: out (reference layout) <- g_outT (channel-major), float4
// ---------------------------------------------------------------------------
__global__ void __launch_bounds__(256) untranspose_kernel(float* __restrict__ out) {
    for (int i4 = blockIdx.x * 256 + threadIdx.x; i4 < N_NODES * FEAT / 4;
         i4 += gridDim.x * 256) {
        int n = i4 / (FEAT / 4);
        int r0 = (i4 - n * (FEAT / 4)) * 4;
        const float* rowT = g_outT + n * FEAT;
        float4 v;
        float* vp = (float*)&v;
        #pragma unroll
        for (int k = 0; k < 4; ++k) {
            int r = r0 + k, rT;
            if (r < 32) {
                rT = r;
            } else if (r < 128) {
                int rr = r - 32;
                int uu = rr / 3, a = rr - uu * 3;
                rT = 32 + a * 32 + uu;
            } else {
                int rr = r - 128;
                int uu = rr / 5, a = rr - uu * 5;
                rT = 128 + a * 32 + uu;
            }
            vp[k] = rowT[rT];
        }
        reinterpret_cast<float4*>(out)[i4] = v;
    }
}

// ---------------------------------------------------------------------------
__device__ __forceinline__ void red1(float* p, float v) {
    asm volatile("red.global.add.f32 [%0], %1;" :: "l"(p), "f"(v) : "memory");
}

// dynamic smem layout (float slots); MSM is 16B-aligned
#define SM_MSM   0                        // 144*64 = 9216
#define SM_YSM   9216                     // 16*64 = 1024
#define SM_W3JT  10240                    // 640
#define SM_CUT   (SM_W3JT + 640)          // 64
#define SM_DIST  (SM_CUT + 64)            // 64
#define SM_SRC   (SM_DIST + 64)           // 64 (int)
#define SM_DST   (SM_SRC + 64)            // 64 (int)
#define SM_TOTALF (SM_DST + 64)           // 11136 floats
#define SMEM_BYTES (SM_TOTALF * 4)        // 44544 B

__global__ void __launch_bounds__(BLK, 3) conv_kernel(
    const float* __restrict__ pos,
    const int* __restrict__ src, const int* __restrict__ dst)
{
    extern __shared__ float smf[];
    float* Msm   = smf + SM_MSM;
    float* ysm   = smf + SM_YSM;
    float* w3jTs = smf + SM_W3JT;
    float* cutsm = smf + SM_CUT;
    float* distsm= smf + SM_DIST;
    int*   srcsm = (int*)(smf + SM_SRC);
    int*   dstsm = (int*)(smf + SM_DST);

    const int t  = threadIdx.x;
    const int u  = t & 31;       // lane == channel
    const int wr = t >> 5;       // warp 0..7 owns edges 8*wr .. 8*wr+7

    // stage w3jT table into smem (640 floats)
    #pragma unroll
    for (int r = 0; r < 3; ++r) {
        int idx = r * BLK + t;
        if (idx < 640) w3jTs[idx] = g_w3jT[idx];
    }

    // ================= Phase A: per-edge geometry (threads 0..63) ==========
    if (t < EPB) {
        int eg = blockIdx.x * EPB + t;
        float cut = 0.f, ux = 0.f, uy = 0.f, uz = 0.f, d = 0.f;
        int sn = 0, dn = 0;
        if (eg < N_EDGES) {
            sn = src[eg]; dn = dst[eg];
            float px = pos[3 * sn]     - pos[3 * dn];
            float py = pos[3 * sn + 1] - pos[3 * dn + 1];
            float pz = pos[3 * sn + 2] - pos[3 * dn + 2];
            d = sqrtf(px * px + py * py + pz * pz);
            float rin = 1.0f / fmaxf(d, 1e-12f);
            ux = px * rin; uy = py * rin; uz = pz * rin;
            if (d < 4.0f) cut = 1.0f;            // live-edge flag
        }
        cutsm[t] = cut;
        distsm[t] = d;
        srcsm[t] = sn; dstsm[t] = dn;
        const float s3 = 1.7320508075688772f, s15 = 3.872983346207417f;
        const float s5h = 1.118033988749895f, s15h = 1.9364916731037085f;
        float* ye = ysm + t * Y_PITCH;
        ye[0] = s3 * uy;
        ye[1] = s3 * uz;
        ye[2] = s3 * ux;
        ye[3] = s15 * ux * uy;
        ye[4] = s15 * uy * uz;
        ye[5] = s5h * (3.0f * uz * uz - 1.0f);
        ye[6] = s15 * ux * uz;
        ye[7] = s15h * (ux * ux - uy * uy);
        ye[8] = 1.0f;
        #pragma unroll
        for (int z = 9; z < Y_PITCH; ++z) ye[z] = 0.f;
    }
    __syncthreads();

    // ================= Phase D: per-edge M matrices (R9 structure) =========
    int   md_yoff[4], md_pos[4], md_row[4];
    #pragma unroll
    for (int g = 0; g < 4; ++g) {
        int idx = g * 32 + u;
        bool v = (idx < 115);
        int p = 10;
        if (v) { while (c_OFF[p] > idx) --p; } else { p = 0; }
        int r  = idx - c_OFF[p];
        int wk = 2 * c_PK[p] + 1;
        int a  = r / wk;
        int c  = r - a * wk;
        int jj = c_PJ[p];
        md_yoff[g] = (jj == 0) ? 8 : ((jj == 1) ? 0 : 3);
        md_pos[g]  = v ? (c_OFFP[p] + r) : 143;       // invalid -> pad slot
        md_row[g]  = idx * 5;
    }
    for (int q = 0; q < 8; ++q) {
        int e = 8 * wr + q;
        if (cutsm[e] == 0.f) continue;      // dead edge (warp-uniform)
        const float* ye = ysm + e * Y_PITCH;
        #pragma unroll
        for (int g = 0; g < 4; ++g) {
            const float* wrow = w3jTs + md_row[g];
            const float* yb = ye + md_yoff[g];
            float a = wrow[0] * yb[0];
            #pragma unroll
            for (int b = 1; b < 5; ++b) a = fmaf(wrow[b], yb[b], a);
            Msm[e * M_PITCH + md_pos[g]] = a;
        }
    }
    __syncwarp();

    // ================= Phase E: radial lookup + tensor product + scatter ===
    #pragma unroll 2
    for (int q = 0; q < 8; ++q) {
        int e = 8 * wr + q;
        if (cutsm[e] == 0.f) continue;      // warp-uniform skip
        int sn = srcsm[e], dn = dstsm[e];

        // radial*cutoff via interleaved-table lerp (d < 4 guaranteed here)
        float x = distsm[e] * ((float)RTAB_N * 0.25f);
        int i0 = (int)x;
        i0 = (i0 > RTAB_N - 1) ? (RTAB_N - 1) : i0;
        float f = x - (float)i0;
        const float2* T = g_rtab2 + i0 * NRAD + u;
        float wv[NPATHS];
        #pragma unroll
        for (int p = 0; p < NPATHS; ++p) {
            float2 ab = T[p * 32];
            wv[p] = fmaf(ab.y - ab.x, f, ab.x);
        }

        // coalesced channel-major node gather
        const float* xb = g_nodesT + (size_t)sn * FEAT;
        float x0r = xb[u];
        float x1r[3], x2r[5];
        #pragma unroll
        for (int a = 0; a < 3; ++a) x1r[a] = xb[32 + a * 32 + u];
        #pragma unroll
        for (int a = 0; a < 5; ++a) x2r[a] = xb[128 + a * 32 + u];

        const float4* M4 = reinterpret_cast<const float4*>(Msm + e * M_PITCH);
        float m0 = 0.f, m1[3] = {0.f, 0.f, 0.f}, m2[5] = {0.f, 0.f, 0.f, 0.f, 0.f};
        float s;

        {   // S1: floats 0..31 -> p0..p4
            float A[32];
            #pragma unroll
            for (int i = 0; i < 8; ++i)
                *reinterpret_cast<float4*>(&A[4 * i]) = M4[i];
            m0 = fmaf(wv[0], x0r * A[0], m0);
            #pragma unroll
            for (int c = 0; c < 3; ++c) m1[c] = fmaf(wv[1], x0r * A[4 + c], m1[c]);
            #pragma unroll
            for (int c = 0; c < 5; ++c) m2[c] = fmaf(wv[2], x0r * A[8 + c], m2[c]);
            #pragma unroll
            for (int c = 0; c < 3; ++c) {
                s = x1r[0] * A[16 + c] + x1r[1] * A[19 + c] + x1r[2] * A[22 + c];
                m1[c] = fmaf(wv[3], s, m1[c]);
            }
            s = x1r[0] * A[28] + x1r[1] * A[29] + x1r[2] * A[30];
            m0 = fmaf(wv[4], s, m0);
        }
        {   // S2: floats 32..59 -> p5, p6
            float A[28];
            #pragma unroll
            for (int i = 0; i < 7; ++i)
                *reinterpret_cast<float4*>(&A[4 * i]) = M4[8 + i];
            #pragma unroll
            for (int c = 0; c < 5; ++c) {
                s = x1r[0] * A[c] + x1r[1] * A[5 + c] + x1r[2] * A[10 + c];
                m2[c] = fmaf(wv[5], s, m2[c]);
            }
            #pragma unroll
            for (int c = 0; c < 3; ++c) {
                s = x1r[0] * A[16 + c] + x1r[1] * A[19 + c] + x1r[2] * A[22 + c];
                m1[c] = fmaf(wv[6], s, m1[c]);
            }
        }
        {   // S3: floats 60..87 -> p7 (2,0,2): A[a*5+c]
            float A[28];
            #pragma unroll
            for (int i = 0; i < 7; ++i)
                *reinterpret_cast<float4*>(&A[4 * i]) = M4[15 + i];
            #pragma unroll
            for (int c = 0; c < 5; ++c) {
                s = 0.f;
                #pragma unroll
                for (int a = 0; a < 5; ++a) s = fmaf(x2r[a], A[a * 5 + c], s);
                m2[c] = fmaf(wv[7], s, m2[c]);
            }
        }
        {   // S4: floats 88..111 -> p8 (A[a*3+c]), p9 (A[16+a])
            float A[24];
            #pragma unroll
            for (int i = 0; i < 6; ++i)
                *reinterpret_cast<float4*>(&A[4 * i]) = M4[22 + i];
            #pragma unroll
            for (int c = 0; c < 3; ++c) {
                s = 0.f;
                #pragma unroll
                for (int a = 0; a < 5; ++a) s = fmaf(x2r[a], A[a * 3 + c], s);
                m1[c] = fmaf(wv[8], s, m1[c]);
            }
            s = 0.f;
            #pragma unroll
            for (int a = 0; a < 5; ++a) s = fmaf(x2r[a], A[16 + a], s);
            m0 = fmaf(wv[9], s, m0);
        }
        {   // S5: floats 112..136 -> p10 (2,2,2): A[a*5+c]
            float A[28];
            #pragma unroll
            for (int i = 0; i < 7; ++i)
                *reinterpret_cast<float4*>(&A[4 * i]) = M4[28 + i];
            #pragma unroll
            for (int c = 0; c < 5; ++c) {
                s = 0.f;
                #pragma unroll
                for (int a = 0; a < 5; ++a) s = fmaf(x2r[a], A[a * 5 + c], s);
                m2[c] = fmaf(wv[10], s, m2[c]);
            }
        }

        // coalesced channel-major atomic scatter (9 x red.f32, no staging)
        float* ob = g_outT + (size_t)dn * FEAT;
        red1(&ob[u], m0);
        #pragma unroll
        for (int a = 0; a < 3; ++a) red1(&ob[32 + a * 32 + u], m1[a]);
        #pragma unroll
        for (int a = 0; a < 5; ++a) red1(&ob[128 + a * 32 + u], m2[a]);
    }
}

// ---------------------------------------------------------------------------
extern "C" void kernel_launch(void* const* d_in, const int* in_sizes, int n_in,
                              void* d_out, int out_size) {
    const float* nodes = (const float*)d_in[0];
    const float* pos   = (const float*)d_in[1];
    const int*   src   = (const int*)d_in[2];
    const int*   dst   = (const int*)d_in[3];
    const float* w1    = (const float*)d_in[4];
    const float* b1    = (const float*)d_in[5];
    const float* w2    = (const float*)d_in[6];
    const float* b2    = (const float*)d_in[7];
    float* out = (float*)d_out;

    setup_kernel<<<SETUP_BLOCKS, 128>>>(nodes);
    rtab_kernel<<<(RTAB_ROWS + 1) / 2, 256>>>(w1, b1, w2, b2);

    cudaFuncSetAttribute(conv_kernel,
                         cudaFuncAttributeMaxDynamicSharedMemorySize, SMEM_BYTES);
    int nblocks = (N_EDGES + EPB - 1) / EPB;
    conv_kernel<<<nblocks, BLK, SMEM_BYTES>>>(pos, src, dst);

    untranspose_kernel<<<1024, 256>>>(out);
}

// round 13
// speedup vs baseline: 1.6082x; 1.6082x over previous
#include <cuda_runtime.h>
#include <cuda_bf16.h>
#include <math.h>

// ---------------------------------------------------------------------------
// Problem constants
// ---------------------------------------------------------------------------
#define N_NODES   10000
#define N_EDGES   250000
#define FF        32
#define HIDDEN    64
#define NPATHS    11
#define FEAT      288
#define NRAD      352

#define EPB       64          // edges per block
#define BLK       256         // threads per block (8 warps, 8 edges/warp)
#define M_PITCH   144         // padded pitch for M[e][elem]; path blocks 16B-aligned
#define Y_PITCH   16          // ysm pitch: 8 harmonics, [8]=1, [9..15]=0

#define RTAB_N    8192        // intervals over d in [0,4]
#define RTAB_ROWS (RTAB_N + 1)

// PATHS = [(0,0,0),(0,1,1),(0,2,2),(1,0,1),(1,1,0),(1,1,2),
//          (1,2,1),(2,0,2),(2,1,1),(2,2,0),(2,2,2)]
__constant__ int c_PI[NPATHS]  = {0,0,0,1,1,1,1,2,2,2,2};
__constant__ int c_PJ[NPATHS]  = {0,1,2,0,1,1,2,0,1,2,2};
__constant__ int c_PK[NPATHS]  = {0,1,2,1,0,2,1,2,1,0,2};
// dense element-offset of path p (sizes {1,3,5,9,3,15,9,25,15,5,25} -> 115)
__constant__ int c_OFF[NPATHS]  = {0,1,4,9,18,21,36,45,70,85,90};
// padded (16B-aligned) offsets within the 144-float per-edge M vector
__constant__ int c_OFFP[NPATHS] = {0,4,8,16,28,32,48,60,88,104,112};
// PATH_W[p]/sqrt(25)
__constant__ float c_PW[NPATHS] = {
    0.11547005383792515f, 0.17320508075688773f, 0.22360679774997896f,
    0.17320508075688773f, 0.11547005383792515f, 0.22360679774997896f,
    0.17320508075688773f, 0.22360679774997896f, 0.17320508075688773f,
    0.11547005383792515f, 0.22360679774997896f};

// Transposed, pre-scaled W3J: w3jT[idx][b] = W3J[p][a, b, c] * PW[p], rows
// padded to 5 (b >= 2j+1 -> 0), idx 115..127 all-zero.
__device__ float g_w3jT[128 * 5];
// Interleaved radial*cutoff table: g_rtab2[i*NRAD+r] = {rad(d_i)[r], rad(d_{i+1})[r]}
__device__ float2 g_rtab2[RTAB_N * NRAD];        // 23 MB static scratch
// Channel-major repacked node features
__device__ float g_nodesT[N_NODES * FEAT];       // 11.5 MB static scratch
// Channel-major output accumulator (transposed back at the end)
__device__ __align__(16) float g_outT[N_NODES * FEAT];

// ---------------------------------------------------------------------------
// Fused setup kernel (4097 blocks x 256 threads):
//   - grid-stride zero of g_outT
//   - grid-stride channel-major node repack
//   - blocks < NPATHS: W3J table (sparse scatter)
//   - all blocks: 2 rows of the radial*cutoff table
// ---------------------------------------------------------------------------
__device__ __forceinline__ float ffact(int n) {
    float r = 1.0f;
    for (int i = 2; i <= n; ++i) r *= (float)i;
    return r;
}

__device__ float su2_cg_f(int j1, int j2, int j3, int m1, int m2, int m3) {
    if (m1 + m2 != m3) return 0.0f;
    float pref = sqrtf((2.0f * j3 + 1.0f) * ffact(j1 + j2 - j3) * ffact(j1 - j2 + j3) *
                       ffact(-j1 + j2 + j3) / ffact(j1 + j2 + j3 + 1));
    pref *= sqrtf(ffact(j3 + m3) * ffact(j3 - m3) * ffact(j1 - m1) * ffact(j1 + m1) *
                  ffact(j2 - m2) * ffact(j2 + m2));
    float s = 0.0f;
    for (int k = 0; k <= j1 + j2 - j3; ++k) {
        int e1 = j1 + j2 - j3 - k, e2 = j1 - m1 - k, e3 = j2 + m2 - k;
        int e4 = j3 - j2 + m1 + k, e5 = j3 - j1 - m2 + k;
        if (e1 < 0 || e2 < 0 || e3 < 0 || e4 < 0 || e5 < 0) continue;
        float term = 1.0f / (ffact(k) * ffact(e1) * ffact(e2) * ffact(e3) *
                             ffact(e4) * ffact(e5));
        s += (k & 1) ? -term : term;
    }
    return pref * s;
}

// nonzeros of row r of q(l), including the (-1j)^l prefactor. Returns count (1 or 2).
__device__ __forceinline__ int qrow(int l, int r, int* col, float* re, float* im) {
    const float is2 = 0.70710678118654752440f;
    int m = r - l;
    int cnt;
    float a[2], b[2];
    if (m < 0) {
        col[0] = l - m; a[0] = is2;  b[0] = 0.f;
        col[1] = l + m; a[1] = 0.f;  b[1] = -is2;
        cnt = 2;
    } else if (m == 0) {
        col[0] = l; a[0] = 1.f; b[0] = 0.f;
        cnt = 1;
    } else {
        float sg = (m & 1) ? -1.f : 1.f;
        col[0] = l + m; a[0] = sg * is2; b[0] = 0.f;
        col[1] = l - m; a[1] = 0.f;      b[1] = sg * is2;
        cnt = 2;
    }
    #pragma unroll
    for (int q = 0; q < 2; ++q) {
        if (q >= cnt) break;
        float A = a[q], B = b[q];
        if (l == 1) { float tA = B, tB = -A; A = tA; B = tB; }   // *(-i)
        else if (l == 2) { A = -A; B = -B; }                     // *(-1)
        re[q] = A; im[q] = B;
    }
    return cnt;
}

#define SETUP_BLOCKS ((RTAB_ROWS + 1) / 2)   // 4097

__global__ void __launch_bounds__(256) setup_kernel(
    const float* __restrict__ nodes,
    const float* __restrict__ w1, const float* __restrict__ b1,
    const float* __restrict__ w2, const float* __restrict__ b2)
{
    int t = threadIdx.x;

    // ---- part 1: grid-stride zero of the transposed accumulator (float4) ----
    {
        float4* o4 = (float4*)g_outT;
        float4 z = make_float4(0.f, 0.f, 0.f, 0.f);
        for (int i = blockIdx.x * blockDim.x + t; i < N_NODES * FEAT / 4;
             i += gridDim.x * blockDim.x)
            o4[i] = z;
    }
    // ---- part 2: grid-stride node repack (channel-major) ----
    for (int idx = blockIdx.x * blockDim.x + t; idx < N_NODES * FEAT;
         idx += gridDim.x * blockDim.x) {
        int n = idx / FEAT, r = idx - n * FEAT;
        float v;
        if (r < 32) {
            v = nodes[n * FEAT + r];
        } else if (r < 128) {
            int a = (r - 32) >> 5, uu = (r - 32) & 31;
            v = nodes[n * FEAT + 32 + uu * 3 + a];
        } else {
            int a = (r - 128) >> 5, uu = (r - 128) & 31;
            v = nodes[n * FEAT + 128 + uu * 5 + a];
        }
        g_nodesT[idx] = v;
    }

    // ---- part 3: W3J (blocks 0..NPATHS-1; block-uniform guard) ----
    __shared__ float C[125], Wre[125], Wim[125];
    __shared__ float sel[2];
    if (blockIdx.x < NPATHS) {
        int p = blockIdx.x;
        int l1 = c_PI[p], l2 = c_PJ[p], l3 = c_PK[p];
        int d1 = 2 * l1 + 1, d2 = 2 * l2 + 1, d3 = 2 * l3 + 1;
        int n = d1 * d2 * d3;

        for (int idx = t; idx < n; idx += blockDim.x) {
            int i = idx / (d2 * d3), k = (idx / d3) % d2, m = idx % d3;
            C[idx] = su2_cg_f(l1, l2, l3, i - l1, k - l2, m - l3);
            Wre[idx] = 0.f; Wim[idx] = 0.f;
        }
        __syncthreads();

        // sparse scatter: each nonzero C entry contributes <=8 outputs
        for (int idx = t; idx < n; idx += blockDim.x) {
            float cc = C[idx];
            if (cc == 0.f) continue;
            int i = idx / (d2 * d3), k = (idx / d3) % d2, m = idx % d3;
            int   c1[2], c2[2], c3[2];
            float a1[2], b1r[2], a2[2], b2r[2], a3[2], b3r[2];
            int n1 = qrow(l1, i, c1, a1, b1r);
            int n2 = qrow(l2, k, c2, a2, b2r);
            int n3 = qrow(l3, m, c3, a3, b3r);
            for (int x = 0; x < n1; ++x)
                for (int y = 0; y < n2; ++y) {
                    float pr = a1[x] * a2[y] - b1r[x] * b2r[y];
                    float pi = a1[x] * b2r[y] + b1r[x] * a2[y];
                    for (int z = 0; z < n3; ++z) {
                        float rr = pr * a3[z] + pi * b3r[z];   // * conj(q3)
                        float ri = pi * a3[z] - pr * b3r[z];
                        int o = (c1[x] * d2 + c2[y]) * d3 + c3[z];
                        atomicAdd(&Wre[o], cc * rr);
                        atomicAdd(&Wim[o], cc * ri);
                    }
                }
        }
        __syncthreads();

        if (t == 0) {
            float nr = 0.0f, ni = 0.0f;
            for (int idx = 0; idx < n; ++idx) {
                nr += Wre[idx] * Wre[idx];
                ni += Wim[idx] * Wim[idx];
            }
            nr = sqrtf(nr); ni = sqrtf(ni);
            sel[0] = (nr >= ni) ? 1.0f : 0.0f;
            sel[1] = (nr >= ni) ? nr : ni;
        }
        __syncthreads();

        bool useRe = sel[0] > 0.5f;
        float scl = c_PW[p] / sel[1];
        const float* W = useRe ? Wre : Wim;

        int off = c_OFF[p];
        int nr5 = d1 * d3 * 5;
        for (int rb = t; rb < nr5; rb += blockDim.x) {
            int r = rb / 5, b = rb - r * 5;
            int a = r / d3, c = r - a * d3;
            float v = (b < d2) ? W[(a * d2 + b) * d3 + c] * scl : 0.f;
            g_w3jT[(off + r) * 5 + b] = v;
        }
        if (p == 0)
            for (int z = t; z < 65; z += blockDim.x) g_w3jT[575 + z] = 0.f;
    }

    // ---- part 4: radial*cutoff table, 2 rows per block ----
    __shared__ float h[2][HIDDEN];
    __shared__ float cutf[2];
    {
        int i0 = blockIdx.x * 2;
        int sub = t >> 6, l64 = t & 63;

        if (sub < 2) {
            int i = i0 + sub;
            if (i < RTAB_ROWS) {
                float d = (float)i * (4.0f / (float)RTAB_N);
                float tt = d * 0.2f;                       // d / BESSEL_END
                float a = b1[l64];
                if (tt > 0.0f && tt < 1.0f) {
                    float cc = 0.6324555320336759f / tt;   // sqrt(2/5)/t
                    #pragma unroll
                    for (int n = 1; n <= 8; ++n) {
                        float bv = cc * sinf((float)n * 3.14159265358979323846f * tt);
                        a = fmaf(bv, w1[(n - 1) * HIDDEN + l64], a);
                    }
                }
                h[sub][l64] = a / (1.0f + __expf(-a));     // silu
                if (l64 == 0) {
                    float cv = 0.f;
                    if (d < 4.0f) {
                        float uu = d * 0.25f;
                        float u2 = uu * uu, u4 = u2 * u2, u5 = u4 * uu;
                        cv = 1.0f - 6.0f * u5 + 5.0f * u5 * uu;
                    }
                    cutf[sub] = cv;
                }
            }
        }
        __syncthreads();

        float* tab = reinterpret_cast<float*>(g_rtab2);
        #pragma unroll
        for (int k = 0; k < 3; ++k) {
            int o = k * 256 + t;
            if (o < 704) {
                int row = (o >= NRAD) ? 1 : 0;
                int r = o - row * NRAD;
                int i = i0 + row;
                if (i < RTAB_ROWS) {
                    float s = b2[r];
                    #pragma unroll 8
                    for (int j = 0; j < HIDDEN; ++j)
                        s = fmaf(h[row][j], w2[j * NRAD + r], s);
                    s *= cutf[row];
                    if (i < RTAB_N) tab[2 * (i * NRAD + r)] = s;            // .x of row i
                    if (i > 0)      tab[2 * ((i - 1) * NRAD + r) + 1] = s;  // .y of row i-1
                }
            }
        }
    }
}

// ---------------------------------------------------------------------------
// Final transpose: out (reference layout) <- g_outT (channel-major)
// ---------------------------------------------------------------------------
__global__ void __launch_bounds__(256) untranspose_kernel(float* __restrict__ out) {
    for (int idx = blockIdx.x * 256 + threadIdx.x; idx < N_NODES * FEAT;
         idx += gridDim.x * 256) {
        int n = idx / FEAT, r = idx - n * FEAT;
        int rT;
        if (r < 32) {
            rT = r;
        } else if (r < 128) {
            int rr = r - 32;
            int uu = rr / 3, a = rr - uu * 3;
            rT = 32 + a * 32 + uu;
        } else {
            int rr = r - 128;
            int uu = rr / 5, a = rr - uu * 5;
            rT = 128 + a * 32 + uu;
        }
        out[idx] = g_outT[n * FEAT + rT];
    }
}

// ---------------------------------------------------------------------------
__device__ __forceinline__ void red1(float* p, float v) {
    asm volatile("red.global.add.f32 [%0], %1;" :: "l"(p), "f"(v) : "memory");
}

// dynamic smem layout (float slots); MSM is 16B-aligned
#define SM_MSM   0                        // 144*64 = 9216
#define SM_YSM   9216                     // 16*64 = 1024
#define SM_W3JT  10240                    // 640
#define SM_CUT   (SM_W3JT + 640)          // 64
#define SM_DIST  (SM_CUT + 64)            // 64
#define SM_SRC   (SM_DIST + 64)           // 64 (int)
#define SM_DST   (SM_SRC + 64)            // 64 (int)
#define SM_TOTALF (SM_DST + 64)           // 11136 floats
#define SMEM_BYTES (SM_TOTALF * 4)        // 44544 B

__global__ void __launch_bounds__(BLK, 3) conv_kernel(
    const float* __restrict__ pos,
    const int* __restrict__ src, const int* __restrict__ dst)
{
    extern __shared__ float smf[];
    float* Msm   = smf + SM_MSM;
    float* ysm   = smf + SM_YSM;
    float* w3jTs = smf + SM_W3JT;
    float* cutsm = smf + SM_CUT;
    float* distsm= smf + SM_DIST;
    int*   srcsm = (int*)(smf + SM_SRC);
    int*   dstsm = (int*)(smf + SM_DST);

    const int t  = threadIdx.x;
    const int u  = t & 31;       // lane == channel
    const int wr = t >> 5;       // warp 0..7 owns edges 8*wr .. 8*wr+7

    // stage w3jT table into smem (640 floats)
    #pragma unroll
    for (int r = 0; r < 3; ++r) {
        int idx = r * BLK + t;
        if (idx < 640) w3jTs[idx] = g_w3jT[idx];
    }

    // ================= Phase A: per-edge geometry (threads 0..63) ==========
    if (t < EPB) {
        int eg = blockIdx.x * EPB + t;
        float cut = 0.f, ux = 0.f, uy = 0.f, uz = 0.f, d = 0.f;
        int sn = 0, dn = 0;
        if (eg < N_EDGES) {
            sn = src[eg]; dn = dst[eg];
            float px = pos[3 * sn]     - pos[3 * dn];
            float py = pos[3 * sn + 1] - pos[3 * dn + 1];
            float pz = pos[3 * sn + 2] - pos[3 * dn + 2];
            d = sqrtf(px * px + py * py + pz * pz);
            float rin = 1.0f / fmaxf(d, 1e-12f);
            ux = px * rin; uy = py * rin; uz = pz * rin;
            if (d < 4.0f) cut = 1.0f;            // live-edge flag
        }
        cutsm[t] = cut;
        distsm[t] = d;
        srcsm[t] = sn; dstsm[t] = dn;
        const float s3 = 1.7320508075688772f, s15 = 3.872983346207417f;
        const float s5h = 1.118033988749895f, s15h = 1.9364916731037085f;
        float* ye = ysm + t * Y_PITCH;
        ye[0] = s3 * uy;
        ye[1] = s3 * uz;
        ye[2] = s3 * ux;
        ye[3] = s15 * ux * uy;
        ye[4] = s15 * uy * uz;
        ye[5] = s5h * (3.0f * uz * uz - 1.0f);
        ye[6] = s15 * ux * uz;
        ye[7] = s15h * (ux * ux - uy * uy);
        ye[8] = 1.0f;
        #pragma unroll
        for (int z = 9; z < Y_PITCH; ++z) ye[z] = 0.f;
    }
    __syncthreads();

    // ================= Phase D: per-edge M matrices ========================
    int   md_yoff[4], md_pos[4], md_row[4];
    #pragma unroll
    for (int g = 0; g < 4; ++g) {
        int idx = g * 32 + u;
        bool v = (idx < 115);
        int p = 10;
        if (v) { while (c_OFF[p] > idx) --p; } else { p = 0; }
        int r  = idx - c_OFF[p];
        int wk = 2 * c_PK[p] + 1;
        int a  = r / wk;
        int c  = r - a * wk;
        int jj = c_PJ[p];
        md_yoff[g] = (jj == 0) ? 8 : ((jj == 1) ? 0 : 3);
        md_pos[g]  = v ? (c_OFFP[p] + r) : 143;       // invalid -> pad slot
        md_row[g]  = idx * 5;
    }
    for (int q = 0; q < 8; ++q) {
        int e = 8 * wr + q;
        if (cutsm[e] == 0.f) continue;      // dead edge (warp-uniform)
        const float* ye = ysm + e * Y_PITCH;
        #pragma unroll
        for (int g = 0; g < 4; ++g) {
            const float* wrow = w3jTs + md_row[g];
            const float* yb = ye + md_yoff[g];
            float a = wrow[0] * yb[0];
            #pragma unroll
            for (int b = 1; b < 5; ++b) a = fmaf(wrow[b], yb[b], a);
            Msm[e * M_PITCH + md_pos[g]] = a;
        }
    }
    __syncwarp();

    // ================= Phase E: radial lookup + tensor product + scatter ===
    #pragma unroll
    for (int q = 0; q < 8; ++q) {
        int e = 8 * wr + q;
        if (cutsm[e] == 0.f) continue;      // warp-uniform skip
        int sn = srcsm[e], dn = dstsm[e];

        // radial*cutoff via interleaved-table lerp (d < 4 guaranteed here)
        float x = distsm[e] * ((float)RTAB_N * 0.25f);
        int i0 = (int)x;
        i0 = (i0 > RTAB_N - 1) ? (RTAB_N - 1) : i0;
        float f = x - (float)i0;
        const float2* T = g_rtab2 + i0 * NRAD + u;
        float wv[NPATHS];
        #pragma unroll
        for (int p = 0; p < NPATHS; ++p) {
            float2 ab = T[p * 32];
            wv[p] = fmaf(ab.y - ab.x, f, ab.x);
        }

        // coalesced channel-major node gather
        const float* xb = g_nodesT + (size_t)sn * FEAT;
        float x0r = xb[u];
        float x1r[3], x2r[5];
        #pragma unroll
        for (int a = 0; a < 3; ++a) x1r[a] = xb[32 + a * 32 + u];
        #pragma unroll
        for (int a = 0; a < 5; ++a) x2r[a] = xb[128 + a * 32 + u];

        const float4* M4 = reinterpret_cast<const float4*>(Msm + e * M_PITCH);
        float m0 = 0.f, m1[3] = {0.f, 0.f, 0.f}, m2[5] = {0.f, 0.f, 0.f, 0.f, 0.f};
        float s;

        {   // S1: floats 0..31 -> p0..p4
            float A[32];
            #pragma unroll
            for (int i = 0; i < 8; ++i)
                *reinterpret_cast<float4*>(&A[4 * i]) = M4[i];
            m0 = fmaf(wv[0], x0r * A[0], m0);
            #pragma unroll
            for (int c = 0; c < 3; ++c) m1[c] = fmaf(wv[1], x0r * A[4 + c], m1[c]);
            #pragma unroll
            for (int c = 0; c < 5; ++c) m2[c] = fmaf(wv[2], x0r * A[8 + c], m2[c]);
            #pragma unroll
            for (int c = 0; c < 3; ++c) {
                s = x1r[0] * A[16 + c] + x1r[1] * A[19 + c] + x1r[2] * A[22 + c];
                m1[c] = fmaf(wv[3], s, m1[c]);
            }
            s = x1r[0] * A[28] + x1r[1] * A[29] + x1r[2] * A[30];
            m0 = fmaf(wv[4], s, m0);
        }
        {   // S2: floats 32..59 -> p5, p6
            float A[28];
            #pragma unroll
            for (int i = 0; i < 7; ++i)
                *reinterpret_cast<float4*>(&A[4 * i]) = M4[8 + i];
            #pragma unroll
            for (int c = 0; c < 5; ++c) {
                s = x1r[0] * A[c] + x1r[1] * A[5 + c] + x1r[2] * A[10 + c];
                m2[c] = fmaf(wv[5], s, m2[c]);
            }
            #pragma unroll
            for (int c = 0; c < 3; ++c) {
                s = x1r[0] * A[16 + c] + x1r[1] * A[19 + c] + x1r[2] * A[22 + c];
                m1[c] = fmaf(wv[6], s, m1[c]);
            }
        }
        {   // S3: floats 60..87 -> p7 (2,0,2): A[a*5+c]
            float A[28];
            #pragma unroll
            for (int i = 0; i < 7; ++i)
                *reinterpret_cast<float4*>(&A[4 * i]) = M4[15 + i];
            #pragma unroll
            for (int c = 0; c < 5; ++c) {
                s = 0.f;
                #pragma unroll
                for (int a = 0; a < 5; ++a) s = fmaf(x2r[a], A[a * 5 + c], s);
                m2[c] = fmaf(wv[7], s, m2[c]);
            }
        }
        {   // S4: floats 88..111 -> p8 (A[a*3+c]), p9 (A[16+a])
            float A[24];
            #pragma unroll
            for (int i = 0; i < 6; ++i)
                *reinterpret_cast<float4*>(&A[4 * i]) = M4[22 + i];
            #pragma unroll
            for (int c = 0; c < 3; ++c) {
                s = 0.f;
                #pragma unroll
                for (int a = 0; a < 5; ++a) s = fmaf(x2r[a], A[a * 3 + c], s);
                m1[c] = fmaf(wv[8], s, m1[c]);
            }
            s = 0.f;
            #pragma unroll
            for (int a = 0; a < 5; ++a) s = fmaf(x2r[a], A[16 + a], s);
            m0 = fmaf(wv[9], s, m0);
        }
        {   // S5: floats 112..136 -> p10 (2,2,2): A[a*5+c]
            float A[28];
            #pragma unroll
            for (int i = 0; i < 7; ++i)
                *reinterpret_cast<float4*>(&A[4 * i]) = M4[28 + i];
            #pragma unroll
            for (int c = 0; c < 5; ++c) {
                s = 0.f;
                #pragma unroll
                for (int a = 0; a < 5; ++a) s = fmaf(x2r[a], A[a * 5 + c], s);
                m2[c] = fmaf(wv[10], s, m2[c]);
            }
        }

        // coalesced channel-major atomic scatter (9 x red.f32, no staging)
        float* ob = g_outT + (size_t)dn * FEAT;
        red1(&ob[u], m0);
        #pragma unroll
        for (int a = 0; a < 3; ++a) red1(&ob[32 + a * 32 + u], m1[a]);
        #pragma unroll
        for (int a = 0; a < 5; ++a) red1(&ob[128 + a * 32 + u], m2[a]);
    }
}

// ---------------------------------------------------------------------------
extern "C" void kernel_launch(void* const* d_in, const int* in_sizes, int n_in,
                              void* d_out, int out_size) {
    const float* nodes = (const float*)d_in[0];
    const float* pos   = (const float*)d_in[1];
    const int*   src   = (const int*)d_in[2];
    const int*   dst   = (const int*)d_in[3];
    const float* w1    = (const float*)d_in[4];
    const float* b1    = (const float*)d_in[5];
    const float* w2    = (const float*)d_in[6];
    const float* b2    = (const float*)d_in[7];
    float* out = (float*)d_out;

    setup_kernel<<<SETUP_BLOCKS, 256>>>(nodes, w1, b1, w2, b2);

    cudaFuncSetAttribute(conv_kernel,
                         cudaFuncAttributeMaxDynamicSharedMemorySize, SMEM_BYTES);
    int nblocks = (N_EDGES + EPB - 1) / EPB;
    conv_kernel<<<nblocks, BLK, SMEM_BYTES>>>(pos, src, dst);

    untranspose_kernel<<<1024, 256>>>(out);
}

// round 14
// speedup vs baseline: 1.8695x; 1.1625x over previous
#include <cuda_runtime.h>
#include <cuda_bf16.h>
#include <math.h>

// ---------------------------------------------------------------------------
// Problem constants
// ---------------------------------------------------------------------------
#define N_NODES   10000
#define N_EDGES   250000
#define FF        32
#define HIDDEN    64
#define NPATHS    11
#define FEAT      288
#define NRAD      352

#define EPB       64          // edges per block
#define BLK       256         // threads per block (8 warps, 8 edges/warp)
#define M_PITCH   144         // padded pitch for M[e][elem]; path blocks 16B-aligned
#define Y_PITCH   16          // ysm pitch: 8 harmonics, [8]=1, [9..15]=0

#define RTAB_N    2048        // intervals over d in [0,4] (lerp err ~1e-5 << 1e-3)
#define RTAB_ROWS (RTAB_N + 1)

// PATHS = [(0,0,0),(0,1,1),(0,2,2),(1,0,1),(1,1,0),(1,1,2),
//          (1,2,1),(2,0,2),(2,1,1),(2,2,0),(2,2,2)]
__constant__ int c_PI[NPATHS]  = {0,0,0,1,1,1,1,2,2,2,2};
__constant__ int c_PJ[NPATHS]  = {0,1,2,0,1,1,2,0,1,2,2};
__constant__ int c_PK[NPATHS]  = {0,1,2,1,0,2,1,2,1,0,2};
// dense element-offset of path p (sizes {1,3,5,9,3,15,9,25,15,5,25} -> 115)
__constant__ int c_OFF[NPATHS]  = {0,1,4,9,18,21,36,45,70,85,90};
// padded (16B-aligned) offsets within the 144-float per-edge M vector
__constant__ int c_OFFP[NPATHS] = {0,4,8,16,28,32,48,60,88,104,112};
// PATH_W[p]/sqrt(25)
__constant__ float c_PW[NPATHS] = {
    0.11547005383792515f, 0.17320508075688773f, 0.22360679774997896f,
    0.17320508075688773f, 0.11547005383792515f, 0.22360679774997896f,
    0.17320508075688773f, 0.22360679774997896f, 0.17320508075688773f,
    0.11547005383792515f, 0.22360679774997896f};

// Transposed, pre-scaled W3J: w3jT[idx][b] = W3J[p][a, b, c] * PW[p], rows
// padded to 5 (b >= 2j+1 -> 0), idx 115..127 all-zero.
__device__ float g_w3jT[128 * 5];
// Interleaved radial*cutoff table: g_rtab2[i*NRAD+r] = {rad(d_i)[r], rad(d_{i+1})[r]}
__device__ float2 g_rtab2[RTAB_N * NRAD];        // 5.8 MB static scratch
// Channel-major repacked node features
__device__ float g_nodesT[N_NODES * FEAT];       // 11.5 MB static scratch
// Channel-major output accumulator (transposed back at the end)
__device__ __align__(16) float g_outT[N_NODES * FEAT];

// ---------------------------------------------------------------------------
// Fused setup kernel (1025 blocks x 256 threads):
//   - grid-stride zero of g_outT
//   - grid-stride channel-major node repack
//   - blocks < NPATHS: W3J table (sparse scatter)
//   - all blocks: 2 rows of the radial*cutoff table
// ---------------------------------------------------------------------------
__device__ __forceinline__ float ffact(int n) {
    float r = 1.0f;
    for (int i = 2; i <= n; ++i) r *= (float)i;
    return r;
}

__device__ float su2_cg_f(int j1, int j2, int j3, int m1, int m2, int m3) {
    if (m1 + m2 != m3) return 0.0f;
    float pref = sqrtf((2.0f * j3 + 1.0f) * ffact(j1 + j2 - j3) * ffact(j1 - j2 + j3) *
                       ffact(-j1 + j2 + j3) / ffact(j1 + j2 + j3 + 1));
    pref *= sqrtf(ffact(j3 + m3) * ffact(j3 - m3) * ffact(j1 - m1) * ffact(j1 + m1) *
                  ffact(j2 - m2) * ffact(j2 + m2));
    float s = 0.0f;
    for (int k = 0; k <= j1 + j2 - j3; ++k) {
        int e1 = j1 + j2 - j3 - k, e2 = j1 - m1 - k, e3 = j2 + m2 - k;
        int e4 = j3 - j2 + m1 + k, e5 = j3 - j1 - m2 + k;
        if (e1 < 0 || e2 < 0 || e3 < 0 || e4 < 0 || e5 < 0) continue;
        float term = 1.0f / (ffact(k) * ffact(e1) * ffact(e2) * ffact(e3) *
                             ffact(e4) * ffact(e5));
        s += (k & 1) ? -term : term;
    }
    return pref * s;
}

// nonzeros of row r of q(l), including the (-1j)^l prefactor. Returns count (1 or 2).
__device__ __forceinline__ int qrow(int l, int r, int* col, float* re, float* im) {
    const float is2 = 0.70710678118654752440f;
    int m = r - l;
    int cnt;
    float a[2], b[2];
    if (m < 0) {
        col[0] = l - m; a[0] = is2;  b[0] = 0.f;
        col[1] = l + m; a[1] = 0.f;  b[1] = -is2;
        cnt = 2;
    } else if (m == 0) {
        col[0] = l; a[0] = 1.f; b[0] = 0.f;
        cnt = 1;
    } else {
        float sg = (m & 1) ? -1.f : 1.f;
        col[0] = l + m; a[0] = sg * is2; b[0] = 0.f;
        col[1] = l - m; a[1] = 0.f;      b[1] = sg * is2;
        cnt = 2;
    }
    #pragma unroll
    for (int q = 0; q < 2; ++q) {
        if (q >= cnt) break;
        float A = a[q], B = b[q];
        if (l == 1) { float tA = B, tB = -A; A = tA; B = tB; }   // *(-i)
        else if (l == 2) { A = -A; B = -B; }                     // *(-1)
        re[q] = A; im[q] = B;
    }
    return cnt;
}

#define SETUP_BLOCKS ((RTAB_ROWS + 1) / 2)   // 1025

__global__ void __launch_bounds__(256) setup_kernel(
    const float* __restrict__ nodes,
    const float* __restrict__ w1, const float* __restrict__ b1,
    const float* __restrict__ w2, const float* __restrict__ b2)
{
    int t = threadIdx.x;

    // ---- part 1: grid-stride zero of the transposed accumulator (float4) ----
    {
        float4* o4 = (float4*)g_outT;
        float4 z = make_float4(0.f, 0.f, 0.f, 0.f);
        for (int i = blockIdx.x * blockDim.x + t; i < N_NODES * FEAT / 4;
             i += gridDim.x * blockDim.x)
            o4[i] = z;
    }
    // ---- part 2: grid-stride node repack (channel-major) ----
    for (int idx = blockIdx.x * blockDim.x + t; idx < N_NODES * FEAT;
         idx += gridDim.x * blockDim.x) {
        int n = idx / FEAT, r = idx - n * FEAT;
        float v;
        if (r < 32) {
            v = nodes[n * FEAT + r];
        } else if (r < 128) {
            int a = (r - 32) >> 5, uu = (r - 32) & 31;
            v = nodes[n * FEAT + 32 + uu * 3 + a];
        } else {
            int a = (r - 128) >> 5, uu = (r - 128) & 31;
            v = nodes[n * FEAT + 128 + uu * 5 + a];
        }
        g_nodesT[idx] = v;
    }

    // ---- part 3: W3J (blocks 0..NPATHS-1; block-uniform guard) ----
    __shared__ float C[125], Wre[125], Wim[125];
    __shared__ float sel[2];
    if (blockIdx.x < NPATHS) {
        int p = blockIdx.x;
        int l1 = c_PI[p], l2 = c_PJ[p], l3 = c_PK[p];
        int d1 = 2 * l1 + 1, d2 = 2 * l2 + 1, d3 = 2 * l3 + 1;
        int n = d1 * d2 * d3;

        for (int idx = t; idx < n; idx += blockDim.x) {
            int i = idx / (d2 * d3), k = (idx / d3) % d2, m = idx % d3;
            C[idx] = su2_cg_f(l1, l2, l3, i - l1, k - l2, m - l3);
            Wre[idx] = 0.f; Wim[idx] = 0.f;
        }
        __syncthreads();

        // sparse scatter: each nonzero C entry contributes <=8 outputs
        for (int idx = t; idx < n; idx += blockDim.x) {
            float cc = C[idx];
            if (cc == 0.f) continue;
            int i = idx / (d2 * d3), k = (idx / d3) % d2, m = idx % d3;
            int   c1[2], c2[2], c3[2];
            float a1[2], b1r[2], a2[2], b2r[2], a3[2], b3r[2];
            int n1 = qrow(l1, i, c1, a1, b1r);
            int n2 = qrow(l2, k, c2, a2, b2r);
            int n3 = qrow(l3, m, c3, a3, b3r);
            for (int x = 0; x < n1; ++x)
                for (int y = 0; y < n2; ++y) {
                    float pr = a1[x] * a2[y] - b1r[x] * b2r[y];
                    float pi = a1[x] * b2r[y] + b1r[x] * a2[y];
                    for (int z = 0; z < n3; ++z) {
                        float rr = pr * a3[z] + pi * b3r[z];   // * conj(q3)
                        float ri = pi * a3[z] - pr * b3r[z];
                        int o = (c1[x] * d2 + c2[y]) * d3 + c3[z];
                        atomicAdd(&Wre[o], cc * rr);
                        atomicAdd(&Wim[o], cc * ri);
                    }
                }
        }
        __syncthreads();

        if (t == 0) {
            float nr = 0.0f, ni = 0.0f;
            for (int idx = 0; idx < n; ++idx) {
                nr += Wre[idx] * Wre[idx];
                ni += Wim[idx] * Wim[idx];
            }
            nr = sqrtf(nr); ni = sqrtf(ni);
            sel[0] = (nr >= ni) ? 1.0f : 0.0f;
            sel[1] = (nr >= ni) ? nr : ni;
        }
        __syncthreads();

        bool useRe = sel[0] > 0.5f;
        float scl = c_PW[p] / sel[1];
        const float* W = useRe ? Wre : Wim;

        int off = c_OFF[p];
        int nr5 = d1 * d3 * 5;
        for (int rb = t; rb < nr5; rb += blockDim.x) {
            int r = rb / 5, b = rb - r * 5;
            int a = r / d3, c = r - a * d3;
            float v = (b < d2) ? W[(a * d2 + b) * d3 + c] * scl : 0.f;
            g_w3jT[(off + r) * 5 + b] = v;
        }
        if (p == 0)
            for (int z = t; z < 65; z += blockDim.x) g_w3jT[575 + z] = 0.f;
    }

    // ---- part 4: radial*cutoff table, 2 rows per block ----
    __shared__ float h[2][HIDDEN];
    __shared__ float cutf[2];
    {
        int i0 = blockIdx.x * 2;
        int sub = t >> 6, l64 = t & 63;

        if (sub < 2) {
            int i = i0 + sub;
            if (i < RTAB_ROWS) {
                float d = (float)i * (4.0f / (float)RTAB_N);
                float tt = d * 0.2f;                       // d / BESSEL_END
                float a = b1[l64];
                if (tt > 0.0f && tt < 1.0f) {
                    float cc = 0.6324555320336759f / tt;   // sqrt(2/5)/t
                    #pragma unroll
                    for (int n = 1; n <= 8; ++n) {
                        float bv = cc * sinf((float)n * 3.14159265358979323846f * tt);
                        a = fmaf(bv, w1[(n - 1) * HIDDEN + l64], a);
                    }
                }
                h[sub][l64] = a / (1.0f + __expf(-a));     // silu
                if (l64 == 0) {
                    float cv = 0.f;
                    if (d < 4.0f) {
                        float uu = d * 0.25f;
                        float u2 = uu * uu, u4 = u2 * u2, u5 = u4 * uu;
                        cv = 1.0f - 6.0f * u5 + 5.0f * u5 * uu;
                    }
                    cutf[sub] = cv;
                }
            }
        }
        __syncthreads();

        float* tab = reinterpret_cast<float*>(g_rtab2);
        #pragma unroll
        for (int k = 0; k < 3; ++k) {
            int o = k * 256 + t;
            if (o < 704) {
                int row = (o >= NRAD) ? 1 : 0;
                int r = o - row * NRAD;
                int i = i0 + row;
                if (i < RTAB_ROWS) {
                    float s = b2[r];
                    #pragma unroll 8
                    for (int j = 0; j < HIDDEN; ++j)
                        s = fmaf(h[row][j], w2[j * NRAD + r], s);
                    s *= cutf[row];
                    if (i < RTAB_N) tab[2 * (i * NRAD + r)] = s;            // .x of row i
                    if (i > 0)      tab[2 * ((i - 1) * NRAD + r) + 1] = s;  // .y of row i-1
                }
            }
        }
    }
}

// ---------------------------------------------------------------------------
// Final transpose: out (reference layout) <- g_outT (channel-major)
// ---------------------------------------------------------------------------
__global__ void __launch_bounds__(256) untranspose_kernel(float* __restrict__ out) {
    for (int idx = blockIdx.x * 256 + threadIdx.x; idx < N_NODES * FEAT;
         idx += gridDim.x * 256) {
        int n = idx / FEAT, r = idx - n * FEAT;
        int rT;
        if (r < 32) {
            rT = r;
        } else if (r < 128) {
            int rr = r - 32;
            int uu = rr / 3, a = rr - uu * 3;
            rT = 32 + a * 32 + uu;
        } else {
            int rr = r - 128;
            int uu = rr / 5, a = rr - uu * 5;
            rT = 128 + a * 32 + uu;
        }
        out[idx] = g_outT[n * FEAT + rT];
    }
}

// ---------------------------------------------------------------------------
__device__ __forceinline__ void red1(float* p, float v) {
    asm volatile("red.global.add.f32 [%0], %1;" :: "l"(p), "f"(v) : "memory");
}

// dynamic smem layout (float slots); MSM is 16B-aligned
#define SM_MSM   0                        // 144*64 = 9216
#define SM_YSM   9216                     // 16*64 = 1024
#define SM_W3JT  10240                    // 640
#define SM_CUT   (SM_W3JT + 640)          // 64
#define SM_DIST  (SM_CUT + 64)            // 64
#define SM_SRC   (SM_DIST + 64)           // 64 (int)
#define SM_DST   (SM_SRC + 64)            // 64 (int)
#define SM_TOTALF (SM_DST + 64)           // 11136 floats
#define SMEM_BYTES (SM_TOTALF * 4)        // 44544 B

__global__ void __launch_bounds__(BLK, 3) conv_kernel(
    const float* __restrict__ pos,
    const int* __restrict__ src, const int* __restrict__ dst)
{
    extern __shared__ float smf[];
    float* Msm   = smf + SM_MSM;
    float* ysm   = smf + SM_YSM;
    float* w3jTs = smf + SM_W3JT;
    float* cutsm = smf + SM_CUT;
    float* distsm= smf + SM_DIST;
    int*   srcsm = (int*)(smf + SM_SRC);
    int*   dstsm = (int*)(smf + SM_DST);

    const int t  = threadIdx.x;
    const int u  = t & 31;       // lane == channel
    const int wr = t >> 5;       // warp 0..7 owns edges 8*wr .. 8*wr+7

    // stage w3jT table into smem (640 floats)
    #pragma unroll
    for (int r = 0; r < 3; ++r) {
        int idx = r * BLK + t;
        if (idx < 640) w3jTs[idx] = g_w3jT[idx];
    }

    // ================= Phase A: per-edge geometry (threads 0..63) ==========
    if (t < EPB) {
        int eg = blockIdx.x * EPB + t;
        float cut = 0.f, ux = 0.f, uy = 0.f, uz = 0.f, d = 0.f;
        int sn = 0, dn = 0;
        if (eg < N_EDGES) {
            sn = src[eg]; dn = dst[eg];
            float px = pos[3 * sn]     - pos[3 * dn];
            float py = pos[3 * sn + 1] - pos[3 * dn + 1];
            float pz = pos[3 * sn + 2] - pos[3 * dn + 2];
            d = sqrtf(px * px + py * py + pz * pz);
            float rin = 1.0f / fmaxf(d, 1e-12f);
            ux = px * rin; uy = py * rin; uz = pz * rin;
            if (d < 4.0f) cut = 1.0f;            // live-edge flag
        }
        cutsm[t] = cut;
        distsm[t] = d;
        srcsm[t] = sn; dstsm[t] = dn;
        const float s3 = 1.7320508075688772f, s15 = 3.872983346207417f;
        const float s5h = 1.118033988749895f, s15h = 1.9364916731037085f;
        float* ye = ysm + t * Y_PITCH;
        ye[0] = s3 * uy;
        ye[1] = s3 * uz;
        ye[2] = s3 * ux;
        ye[3] = s15 * ux * uy;
        ye[4] = s15 * uy * uz;
        ye[5] = s5h * (3.0f * uz * uz - 1.0f);
        ye[6] = s15 * ux * uz;
        ye[7] = s15h * (ux * ux - uy * uy);
        ye[8] = 1.0f;
        #pragma unroll
        for (int z = 9; z < Y_PITCH; ++z) ye[z] = 0.f;
    }
    __syncthreads();

    // ================= Phase D: per-edge M matrices ========================
    int   md_yoff[4], md_pos[4], md_row[4];
    #pragma unroll
    for (int g = 0; g < 4; ++g) {
        int idx = g * 32 + u;
        bool v = (idx < 115);
        int p = 10;
        if (v) { while (c_OFF[p] > idx) --p; } else { p = 0; }
        int r  = idx - c_OFF[p];
        int wk = 2 * c_PK[p] + 1;
        int a  = r / wk;
        int c  = r - a * wk;
        int jj = c_PJ[p];
        md_yoff[g] = (jj == 0) ? 8 : ((jj == 1) ? 0 : 3);
        md_pos[g]  = v ? (c_OFFP[p] + r) : 143;       // invalid -> pad slot
        md_row[g]  = idx * 5;
    }
    for (int q = 0; q < 8; ++q) {
        int e = 8 * wr + q;
        if (cutsm[e] == 0.f) continue;      // dead edge (warp-uniform)
        const float* ye = ysm + e * Y_PITCH;
        #pragma unroll
        for (int g = 0; g < 4; ++g) {
            const float* wrow = w3jTs + md_row[g];
            const float* yb = ye + md_yoff[g];
            float a = wrow[0] * yb[0];
            #pragma unroll
            for (int b = 1; b < 5; ++b) a = fmaf(wrow[b], yb[b], a);
            Msm[e * M_PITCH + md_pos[g]] = a;
        }
    }
    __syncwarp();

    // ================= Phase E: radial lookup + tensor product + scatter ===
    #pragma unroll
    for (int q = 0; q < 8; ++q) {
        int e = 8 * wr + q;
        if (cutsm[e] == 0.f) continue;      // warp-uniform skip
        int sn = srcsm[e], dn = dstsm[e];

        // radial*cutoff via interleaved-table lerp (d < 4 guaranteed here)
        float x = distsm[e] * ((float)RTAB_N * 0.25f);
        int i0 = (int)x;
        i0 = (i0 > RTAB_N - 1) ? (RTAB_N - 1) : i0;
        float f = x - (float)i0;
        const float2* T = g_rtab2 + i0 * NRAD + u;
        float wv[NPATHS];
        #pragma unroll
        for (int p = 0; p < NPATHS; ++p) {
            float2 ab = T[p * 32];
            wv[p] = fmaf(ab.y - ab.x, f, ab.x);
        }

        // coalesced channel-major node gather
        const float* xb = g_nodesT + (size_t)sn * FEAT;
        float x0r = xb[u];
        float x1r[3], x2r[5];
        #pragma unroll
        for (int a = 0; a < 3; ++a) x1r[a] = xb[32 + a * 32 + u];
        #pragma unroll
        for (int a = 0; a < 5; ++a) x2r[a] = xb[128 + a * 32 + u];

        const float4* M4 = reinterpret_cast<const float4*>(Msm + e * M_PITCH);
        float m0 = 0.f, m1[3] = {0.f, 0.f, 0.f}, m2[5] = {0.f, 0.f, 0.f, 0.f, 0.f};
        float s;

        {   // S1: floats 0..31 -> p0..p4
            float A[32];
            #pragma unroll
            for (int i = 0; i < 8; ++i)
                *reinterpret_cast<float4*>(&A[4 * i]) = M4[i];
            m0 = fmaf(wv[0], x0r * A[0], m0);
            #pragma unroll
            for (int c = 0; c < 3; ++c) m1[c] = fmaf(wv[1], x0r * A[4 + c], m1[c]);
            #pragma unroll
            for (int c = 0; c < 5; ++c) m2[c] = fmaf(wv[2], x0r * A[8 + c], m2[c]);
            #pragma unroll
            for (int c = 0; c < 3; ++c) {
                s = x1r[0] * A[16 + c] + x1r[1] * A[19 + c] + x1r[2] * A[22 + c];
                m1[c] = fmaf(wv[3], s, m1[c]);
            }
            s = x1r[0] * A[28] + x1r[1] * A[29] + x1r[2] * A[30];
            m0 = fmaf(wv[4], s, m0);
        }
        {   // S2: floats 32..59 -> p5, p6
            float A[28];
            #pragma unroll
            for (int i = 0; i < 7; ++i)
                *reinterpret_cast<float4*>(&A[4 * i]) = M4[8 + i];
            #pragma unroll
            for (int c = 0; c < 5; ++c) {
                s = x1r[0] * A[c] + x1r[1] * A[5 + c] + x1r[2] * A[10 + c];
                m2[c] = fmaf(wv[5], s, m2[c]);
            }
            #pragma unroll
            for (int c = 0; c < 3; ++c) {
                s = x1r[0] * A[16 + c] + x1r[1] * A[19 + c] + x1r[2] * A[22 + c];
                m1[c] = fmaf(wv[6], s, m1[c]);
            }
        }
        {   // S3: floats 60..87 -> p7 (2,0,2): A[a*5+c]
            float A[28];
            #pragma unroll
            for (int i = 0; i < 7; ++i)
                *reinterpret_cast<float4*>(&A[4 * i]) = M4[15 + i];
            #pragma unroll
            for (int c = 0; c < 5; ++c) {
                s = 0.f;
                #pragma unroll
                for (int a = 0; a < 5; ++a) s = fmaf(x2r[a], A[a * 5 + c], s);
                m2[c] = fmaf(wv[7], s, m2[c]);
            }
        }
        {   // S4: floats 88..111 -> p8 (A[a*3+c]), p9 (A[16+a])
            float A[24];
            #pragma unroll
            for (int i = 0; i < 6; ++i)
                *reinterpret_cast<float4*>(&A[4 * i]) = M4[22 + i];
            #pragma unroll
            for (int c = 0; c < 3; ++c) {
                s = 0.f;
                #pragma unroll
                for (int a = 0; a < 5; ++a) s = fmaf(x2r[a], A[a * 3 + c], s);
                m1[c] = fmaf(wv[8], s, m1[c]);
            }
            s = 0.f;
            #pragma unroll
            for (int a = 0; a < 5; ++a) s = fmaf(x2r[a], A[16 + a], s);
            m0 = fmaf(wv[9], s, m0);
        }
        {   // S5: floats 112..136 -> p10 (2,2,2): A[a*5+c]
            float A[28];
            #pragma unroll
            for (int i = 0; i < 7; ++i)
                *reinterpret_cast<float4*>(&A[4 * i]) = M4[28 + i];
            #pragma unroll
            for (int c = 0; c < 5; ++c) {
                s = 0.f;
                #pragma unroll
                for (int a = 0; a < 5; ++a) s = fmaf(x2r[a], A[a * 5 + c], s);
                m2[c] = fmaf(wv[10], s, m2[c]);
            }
        }

        // coalesced channel-major atomic scatter (9 x red.f32, no staging)
        float* ob = g_outT + (size_t)dn * FEAT;
        red1(&ob[u], m0);
        #pragma unroll
        for (int a = 0; a < 3; ++a) red1(&ob[32 + a * 32 + u], m1[a]);
        #pragma unroll
        for (int a = 0; a < 5; ++a) red1(&ob[128 + a * 32 + u], m2[a]);
    }
}

// ---------------------------------------------------------------------------
extern "C" void kernel_launch(void* const* d_in, const int* in_sizes, int n_in,
                              void* d_out, int out_size) {
    const float* nodes = (const float*)d_in[0];
    const float* pos   = (const float*)d_in[1];
    const int*   src   = (const int*)d_in[2];
    const int*   dst   = (const int*)d_in[3];
    const float* w1    = (const float*)d_in[4];
    const float* b1    = (const float*)d_in[5];
    const float* w2    = (const float*)d_in[6];
    const float* b2    = (const float*)d_in[7];
    float* out = (float*)d_out;

    setup_kernel<<<SETUP_BLOCKS, 256>>>(nodes, w1, b1, w2, b2);

    cudaFuncSetAttribute(conv_kernel,
                         cudaFuncAttributeMaxDynamicSharedMemorySize, SMEM_BYTES);
    int nblocks = (N_EDGES + EPB - 1) / EPB;
    conv_kernel<<<nblocks, BLK, SMEM_BYTES>>>(pos, src, dst);

    untranspose_kernel<<<2048, 256>>>(out);
}

// round 15
// speedup vs baseline: 1.9186x; 1.0262x over previous
#include <cuda_runtime.h>
#include <cuda_bf16.h>
#include <math.h>

// ---------------------------------------------------------------------------
// Problem constants
// ---------------------------------------------------------------------------
#define N_NODES   10000
#define N_EDGES   250000
#define FF        32
#define HIDDEN    64
#define NPATHS    11
#define FEAT      288
#define NRAD      352

#define EPB       64          // edges per block
#define BLK       256         // threads per block (8 warps, 8 edges/warp)
#define M_PITCH   144         // padded pitch for M[e][elem]; path blocks 16B-aligned
#define Y_PITCH   16          // ysm pitch: 8 harmonics, [8]=1, [9..15]=0

#define RTAB_N    1024        // intervals over d in [0,4] (lerp err ~3e-5 << 1e-3)
#define RTAB_ROWS (RTAB_N + 1)
#define ROWS_PER_BLK 8
#define RTAB_BLKS ((RTAB_ROWS + ROWS_PER_BLK - 1) / ROWS_PER_BLK)   // 129

// PATHS = [(0,0,0),(0,1,1),(0,2,2),(1,0,1),(1,1,0),(1,1,2),
//          (1,2,1),(2,0,2),(2,1,1),(2,2,0),(2,2,2)]
__constant__ int c_PI[NPATHS]  = {0,0,0,1,1,1,1,2,2,2,2};
__constant__ int c_PJ[NPATHS]  = {0,1,2,0,1,1,2,0,1,2,2};
__constant__ int c_PK[NPATHS]  = {0,1,2,1,0,2,1,2,1,0,2};
// dense element-offset of path p (sizes {1,3,5,9,3,15,9,25,15,5,25} -> 115)
__constant__ int c_OFF[NPATHS]  = {0,1,4,9,18,21,36,45,70,85,90};
// padded (16B-aligned) offsets within the 144-float per-edge M vector
__constant__ int c_OFFP[NPATHS] = {0,4,8,16,28,32,48,60,88,104,112};
// PATH_W[p]/sqrt(25)
__constant__ float c_PW[NPATHS] = {
    0.11547005383792515f, 0.17320508075688773f, 0.22360679774997896f,
    0.17320508075688773f, 0.11547005383792515f, 0.22360679774997896f,
    0.17320508075688773f, 0.22360679774997896f, 0.17320508075688773f,
    0.11547005383792515f, 0.22360679774997896f};

// Transposed, pre-scaled W3J: w3jT[idx][b] = W3J[p][a, b, c] * PW[p], rows
// padded to 5 (b >= 2j+1 -> 0), idx 115..127 all-zero.
__device__ float g_w3jT[128 * 5];
// Interleaved radial*cutoff table: g_rtab2[i*NRAD+r] = {rad(d_i)[r], rad(d_{i+1})[r]}
__device__ float2 g_rtab2[RTAB_N * NRAD];        // 2.9 MB static scratch
// Channel-major repacked node features
__device__ float g_nodesT[N_NODES * FEAT];       // 11.5 MB static scratch
// Channel-major output accumulator (transposed back at the end)
__device__ __align__(16) float g_outT[N_NODES * FEAT];

// ---------------------------------------------------------------------------
// Fused setup kernel (1024 blocks x 256 threads):
//   - grid-stride zero of g_outT
//   - grid-stride channel-major node repack
//   - blocks [RTAB_BLKS, RTAB_BLKS+NPATHS): W3J table (sparse scatter)
//   - blocks [0, RTAB_BLKS): 8 rows of the radial*cutoff table (w2 reused 8x)
// ---------------------------------------------------------------------------
__device__ __forceinline__ float ffact(int n) {
    float r = 1.0f;
    for (int i = 2; i <= n; ++i) r *= (float)i;
    return r;
}

__device__ float su2_cg_f(int j1, int j2, int j3, int m1, int m2, int m3) {
    if (m1 + m2 != m3) return 0.0f;
    float pref = sqrtf((2.0f * j3 + 1.0f) * ffact(j1 + j2 - j3) * ffact(j1 - j2 + j3) *
                       ffact(-j1 + j2 + j3) / ffact(j1 + j2 + j3 + 1));
    pref *= sqrtf(ffact(j3 + m3) * ffact(j3 - m3) * ffact(j1 - m1) * ffact(j1 + m1) *
                  ffact(j2 - m2) * ffact(j2 + m2));
    float s = 0.0f;
    for (int k = 0; k <= j1 + j2 - j3; ++k) {
        int e1 = j1 + j2 - j3 - k, e2 = j1 - m1 - k, e3 = j2 + m2 - k;
        int e4 = j3 - j2 + m1 + k, e5 = j3 - j1 - m2 + k;
        if (e1 < 0 || e2 < 0 || e3 < 0 || e4 < 0 || e5 < 0) continue;
        float term = 1.0f / (ffact(k) * ffact(e1) * ffact(e2) * ffact(e3) *
                             ffact(e4) * ffact(e5));
        s += (k & 1) ? -term : term;
    }
    return pref * s;
}

// nonzeros of row r of q(l), including the (-1j)^l prefactor. Returns count (1 or 2).
__device__ __forceinline__ int qrow(int l, int r, int* col, float* re, float* im) {
    const float is2 = 0.70710678118654752440f;
    int m = r - l;
    int cnt;
    float a[2], b[2];
    if (m < 0) {
        col[0] = l - m; a[0] = is2;  b[0] = 0.f;
        col[1] = l + m; a[1] = 0.f;  b[1] = -is2;
        cnt = 2;
    } else if (m == 0) {
        col[0] = l; a[0] = 1.f; b[0] = 0.f;
        cnt = 1;
    } else {
        float sg = (m & 1) ? -1.f : 1.f;
        col[0] = l + m; a[0] = sg * is2; b[0] = 0.f;
        col[1] = l - m; a[1] = 0.f;      b[1] = sg * is2;
        cnt = 2;
    }
    #pragma unroll
    for (int q = 0; q < 2; ++q) {
        if (q >= cnt) break;
        float A = a[q], B = b[q];
        if (l == 1) { float tA = B, tB = -A; A = tA; B = tB; }   // *(-i)
        else if (l == 2) { A = -A; B = -B; }                     // *(-1)
        re[q] = A; im[q] = B;
    }
    return cnt;
}

#define SETUP_BLOCKS 1024

__global__ void __launch_bounds__(256) setup_kernel(
    const float* __restrict__ nodes,
    const float* __restrict__ w1, const float* __restrict__ b1,
    const float* __restrict__ w2, const float* __restrict__ b2)
{
    int t = threadIdx.x;

    // ---- part 1: grid-stride zero of the transposed accumulator (float4) ----
    {
        float4* o4 = (float4*)g_outT;
        float4 z = make_float4(0.f, 0.f, 0.f, 0.f);
        for (int i = blockIdx.x * blockDim.x + t; i < N_NODES * FEAT / 4;
             i += gridDim.x * blockDim.x)
            o4[i] = z;
    }
    // ---- part 2: grid-stride node repack (channel-major) ----
    for (int idx = blockIdx.x * blockDim.x + t; idx < N_NODES * FEAT;
         idx += gridDim.x * blockDim.x) {
        int n = idx / FEAT, r = idx - n * FEAT;
        float v;
        if (r < 32) {
            v = nodes[n * FEAT + r];
        } else if (r < 128) {
            int a = (r - 32) >> 5, uu = (r - 32) & 31;
            v = nodes[n * FEAT + 32 + uu * 3 + a];
        } else {
            int a = (r - 128) >> 5, uu = (r - 128) & 31;
            v = nodes[n * FEAT + 128 + uu * 5 + a];
        }
        g_nodesT[idx] = v;
    }

    // ---- part 3: W3J (blocks RTAB_BLKS .. RTAB_BLKS+NPATHS-1) ----
    __shared__ float C[125], Wre[125], Wim[125];
    __shared__ float sel[2];
    if (blockIdx.x >= RTAB_BLKS && blockIdx.x < RTAB_BLKS + NPATHS) {
        int p = blockIdx.x - RTAB_BLKS;
        int l1 = c_PI[p], l2 = c_PJ[p], l3 = c_PK[p];
        int d1 = 2 * l1 + 1, d2 = 2 * l2 + 1, d3 = 2 * l3 + 1;
        int n = d1 * d2 * d3;

        for (int idx = t; idx < n; idx += blockDim.x) {
            int i = idx / (d2 * d3), k = (idx / d3) % d2, m = idx % d3;
            C[idx] = su2_cg_f(l1, l2, l3, i - l1, k - l2, m - l3);
            Wre[idx] = 0.f; Wim[idx] = 0.f;
        }
        __syncthreads();

        // sparse scatter: each nonzero C entry contributes <=8 outputs
        for (int idx = t; idx < n; idx += blockDim.x) {
            float cc = C[idx];
            if (cc == 0.f) continue;
            int i = idx / (d2 * d3), k = (idx / d3) % d2, m = idx % d3;
            int   c1[2], c2[2], c3[2];
            float a1[2], b1r[2], a2[2], b2r[2], a3[2], b3r[2];
            int n1 = qrow(l1, i, c1, a1, b1r);
            int n2 = qrow(l2, k, c2, a2, b2r);
            int n3 = qrow(l3, m, c3, a3, b3r);
            for (int x = 0; x < n1; ++x)
                for (int y = 0; y < n2; ++y) {
                    float pr = a1[x] * a2[y] - b1r[x] * b2r[y];
                    float pi = a1[x] * b2r[y] + b1r[x] * a2[y];
                    for (int z = 0; z < n3; ++z) {
                        float rr = pr * a3[z] + pi * b3r[z];   // * conj(q3)
                        float ri = pi * a3[z] - pr * b3r[z];
                        int o = (c1[x] * d2 + c2[y]) * d3 + c3[z];
                        atomicAdd(&Wre[o], cc * rr);
                        atomicAdd(&Wim[o], cc * ri);
                    }
                }
        }
        __syncthreads();

        if (t == 0) {
            float nr = 0.0f, ni = 0.0f;
            for (int idx = 0; idx < n; ++idx) {
                nr += Wre[idx] * Wre[idx];
                ni += Wim[idx] * Wim[idx];
            }
            nr = sqrtf(nr); ni = sqrtf(ni);
            sel[0] = (nr >= ni) ? 1.0f : 0.0f;
            sel[1] = (nr >= ni) ? nr : ni;
        }
        __syncthreads();

        bool useRe = sel[0] > 0.5f;
        float scl = c_PW[p] / sel[1];
        const float* W = useRe ? Wre : Wim;

        int off = c_OFF[p];
        int nr5 = d1 * d3 * 5;
        for (int rb = t; rb < nr5; rb += blockDim.x) {
            int r = rb / 5, b = rb - r * 5;
            int a = r / d3, c = r - a * d3;
            float v = (b < d2) ? W[(a * d2 + b) * d3 + c] * scl : 0.f;
            g_w3jT[(off + r) * 5 + b] = v;
        }
        if (p == 0)
            for (int z = t; z < 65; z += blockDim.x) g_w3jT[575 + z] = 0.f;
    }

    // ---- part 4: radial*cutoff table, 8 rows per block (blocks < RTAB_BLKS) ----
    __shared__ float h[ROWS_PER_BLK][HIDDEN];
    __shared__ float cutf[ROWS_PER_BLK];
    if (blockIdx.x < RTAB_BLKS) {
        int i0 = blockIdx.x * ROWS_PER_BLK;

        // hidden activations for the 8 rows (512 values, 256 threads x2)
        for (int z = t; z < ROWS_PER_BLK * HIDDEN; z += 256) {
            int row = z >> 6, l64 = z & 63;
            int i = i0 + row;
            if (i < RTAB_ROWS) {
                float d = (float)i * (4.0f / (float)RTAB_N);
                float tt = d * 0.2f;                       // d / BESSEL_END
                float a = b1[l64];
                if (tt > 0.0f && tt < 1.0f) {
                    float cc = 0.6324555320336759f / tt;   // sqrt(2/5)/t
                    #pragma unroll
                    for (int n = 1; n <= 8; ++n) {
                        float bv = cc * sinf((float)n * 3.14159265358979323846f * tt);
                        a = fmaf(bv, w1[(n - 1) * HIDDEN + l64], a);
                    }
                }
                h[row][l64] = a / (1.0f + __expf(-a));     // silu
            } else {
                h[row][l64] = 0.f;
            }
        }
        if (t < ROWS_PER_BLK) {
            int i = i0 + t;
            float cv = 0.f;
            if (i < RTAB_ROWS) {
                float d = (float)i * (4.0f / (float)RTAB_N);
                if (d < 4.0f) {
                    float uu = d * 0.25f;
                    float u2 = uu * uu, u4 = u2 * u2, u5 = u4 * uu;
                    cv = 1.0f - 6.0f * u5 + 5.0f * u5 * uu;
                }
            }
            cutf[t] = cv;
        }
        __syncthreads();

        float* tab = reinterpret_cast<float*>(g_rtab2);
        for (int r = t; r < NRAD; r += 256) {
            float acc[ROWS_PER_BLK];
            float bb = b2[r];
            #pragma unroll
            for (int row = 0; row < ROWS_PER_BLK; ++row) acc[row] = bb;
            #pragma unroll 4
            for (int j = 0; j < HIDDEN; ++j) {
                float w = w2[j * NRAD + r];
                #pragma unroll
                for (int row = 0; row < ROWS_PER_BLK; ++row)
                    acc[row] = fmaf(h[row][j], w, acc[row]);
            }
            #pragma unroll
            for (int row = 0; row < ROWS_PER_BLK; ++row) {
                int i = i0 + row;
                if (i < RTAB_ROWS) {
                    float s = acc[row] * cutf[row];
                    if (i < RTAB_N) tab[2 * (i * NRAD + r)] = s;            // .x row i
                    if (i > 0)      tab[2 * ((i - 1) * NRAD + r) + 1] = s;  // .y row i-1
                }
            }
        }
    }
}

// ---------------------------------------------------------------------------
// Final transpose: out (reference layout) <- g_outT (channel-major)
// ---------------------------------------------------------------------------
__global__ void __launch_bounds__(256) untranspose_kernel(float* __restrict__ out) {
    for (int idx = blockIdx.x * 256 + threadIdx.x; idx < N_NODES * FEAT;
         idx += gridDim.x * 256) {
        int n = idx / FEAT, r = idx - n * FEAT;
        int rT;
        if (r < 32) {
            rT = r;
        } else if (r < 128) {
            int rr = r - 32;
            int uu = rr / 3, a = rr - uu * 3;
            rT = 32 + a * 32 + uu;
        } else {
            int rr = r - 128;
            int uu = rr / 5, a = rr - uu * 5;
            rT = 128 + a * 32 + uu;
        }
        out[idx] = g_outT[n * FEAT + rT];
    }
}

// ---------------------------------------------------------------------------
__device__ __forceinline__ void red1(float* p, float v) {
    asm volatile("red.global.add.f32 [%0], %1;" :: "l"(p), "f"(v) : "memory");
}

// dynamic smem layout (float slots); MSM is 16B-aligned
#define SM_MSM   0                        // 144*64 = 9216
#define SM_YSM   9216                     // 16*64 = 1024
#define SM_W3JT  10240                    // 640
#define SM_CUT   (SM_W3JT + 640)          // 64
#define SM_DIST  (SM_CUT + 64)            // 64
#define SM_SRC   (SM_DIST + 64)           // 64 (int)
#define SM_DST   (SM_SRC + 64)            // 64 (int)
#define SM_TOTALF (SM_DST + 64)           // 11136 floats
#define SMEM_BYTES (SM_TOTALF * 4)        // 44544 B

__global__ void __launch_bounds__(BLK, 3) conv_kernel(
    const float* __restrict__ pos,
    const int* __restrict__ src, const int* __restrict__ dst)
{
    extern __shared__ float smf[];
    float* Msm   = smf + SM_MSM;
    float* ysm   = smf + SM_YSM;
    float* w3jTs = smf + SM_W3JT;
    float* cutsm = smf + SM_CUT;
    float* distsm= smf + SM_DIST;
    int*   srcsm = (int*)(smf + SM_SRC);
    int*   dstsm = (int*)(smf + SM_DST);

    const int t  = threadIdx.x;
    const int u  = t & 31;       // lane == channel
    const int wr = t >> 5;       // warp 0..7 owns edges 8*wr .. 8*wr+7

    // stage w3jT table into smem (640 floats)
    #pragma unroll
    for (int r = 0; r < 3; ++r) {
        int idx = r * BLK + t;
        if (idx < 640) w3jTs[idx] = g_w3jT[idx];
    }

    // ================= Phase A: per-edge geometry (threads 0..63) ==========
    if (t < EPB) {
        int eg = blockIdx.x * EPB + t;
        float cut = 0.f, ux = 0.f, uy = 0.f, uz = 0.f, d = 0.f;
        int sn = 0, dn = 0;
        if (eg < N_EDGES) {
            sn = src[eg]; dn = dst[eg];
            float px = pos[3 * sn]     - pos[3 * dn];
            float py = pos[3 * sn + 1] - pos[3 * dn + 1];
            float pz = pos[3 * sn + 2] - pos[3 * dn + 2];
            d = sqrtf(px * px + py * py + pz * pz);
            float rin = 1.0f / fmaxf(d, 1e-12f);
            ux = px * rin; uy = py * rin; uz = pz * rin;
            if (d < 4.0f) cut = 1.0f;            // live-edge flag
        }
        cutsm[t] = cut;
        distsm[t] = d;
        srcsm[t] = sn; dstsm[t] = dn;
        const float s3 = 1.7320508075688772f, s15 = 3.872983346207417f;
        const float s5h = 1.118033988749895f, s15h = 1.9364916731037085f;
        float* ye = ysm + t * Y_PITCH;
        ye[0] = s3 * uy;
        ye[1] = s3 * uz;
        ye[2] = s3 * ux;
        ye[3] = s15 * ux * uy;
        ye[4] = s15 * uy * uz;
        ye[5] = s5h * (3.0f * uz * uz - 1.0f);
        ye[6] = s15 * ux * uz;
        ye[7] = s15h * (ux * ux - uy * uy);
        ye[8] = 1.0f;
        #pragma unroll
        for (int z = 9; z < Y_PITCH; ++z) ye[z] = 0.f;
    }
    __syncthreads();

    // ================= Phase D: per-edge M matrices ========================
    int   md_yoff[4], md_pos[4], md_row[4];
    #pragma unroll
    for (int g = 0; g < 4; ++g) {
        int idx = g * 32 + u;
        bool v = (idx < 115);
        int p = 10;
        if (v) { while (c_OFF[p] > idx) --p; } else { p = 0; }
        int r  = idx - c_OFF[p];
        int wk = 2 * c_PK[p] + 1;
        int a  = r / wk;
        int c  = r - a * wk;
        int jj = c_PJ[p];
        md_yoff[g] = (jj == 0) ? 8 : ((jj == 1) ? 0 : 3);
        md_pos[g]  = v ? (c_OFFP[p] + r) : 143;       // invalid -> pad slot
        md_row[g]  = idx * 5;
    }
    for (int q = 0; q < 8; ++q) {
        int e = 8 * wr + q;
        if (cutsm[e] == 0.f) continue;      // dead edge (warp-uniform)
        const float* ye = ysm + e * Y_PITCH;
        #pragma unroll
        for (int g = 0; g < 4; ++g) {
            const float* wrow = w3jTs + md_row[g];
            const float* yb = ye + md_yoff[g];
            float a = wrow[0] * yb[0];
            #pragma unroll
            for (int b = 1; b < 5; ++b) a = fmaf(wrow[b], yb[b], a);
            Msm[e * M_PITCH + md_pos[g]] = a;
        }
    }
    __syncwarp();

    // ================= Phase E: radial lookup + tensor product + scatter ===
    #pragma unroll
    for (int q = 0; q < 8; ++q) {
        int e = 8 * wr + q;
        if (cutsm[e] == 0.f) continue;      // warp-uniform skip
        int sn = srcsm[e], dn = dstsm[e];

        // radial*cutoff via interleaved-table lerp (d < 4 guaranteed here)
        float x = distsm[e] * ((float)RTAB_N * 0.25f);
        int i0 = (int)x;
        i0 = (i0 > RTAB_N - 1) ? (RTAB_N - 1) : i0;
        float f = x - (float)i0;
        const float2* T = g_rtab2 + i0 * NRAD + u;
        float wv[NPATHS];
        #pragma unroll
        for (int p = 0; p < NPATHS; ++p) {
            float2 ab = T[p * 32];
            wv[p] = fmaf(ab.y - ab.x, f, ab.x);
        }

        // coalesced channel-major node gather
        const float* xb = g_nodesT + (size_t)sn * FEAT;
        float x0r = xb[u];
        float x1r[3], x2r[5];
        #pragma unroll
        for (int a = 0; a < 3; ++a) x1r[a] = xb[32 + a * 32 + u];
        #pragma unroll
        for (int a = 0; a < 5; ++a) x2r[a] = xb[128 + a * 32 + u];

        const float4* M4 = reinterpret_cast<const float4*>(Msm + e * M_PITCH);
        float m0 = 0.f, m1[3] = {0.f, 0.f, 0.f}, m2[5] = {0.f, 0.f, 0.f, 0.f, 0.f};
        float s;

        {   // S1: floats 0..31 -> p0..p4
            float A[32];
            #pragma unroll
            for (int i = 0; i < 8; ++i)
                *reinterpret_cast<float4*>(&A[4 * i]) = M4[i];
            m0 = fmaf(wv[0], x0r * A[0], m0);
            #pragma unroll
            for (int c = 0; c < 3; ++c) m1[c] = fmaf(wv[1], x0r * A[4 + c], m1[c]);
            #pragma unroll
            for (int c = 0; c < 5; ++c) m2[c] = fmaf(wv[2], x0r * A[8 + c], m2[c]);
            #pragma unroll
            for (int c = 0; c < 3; ++c) {
                s = x1r[0] * A[16 + c] + x1r[1] * A[19 + c] + x1r[2] * A[22 + c];
                m1[c] = fmaf(wv[3], s, m1[c]);
            }
            s = x1r[0] * A[28] + x1r[1] * A[29] + x1r[2] * A[30];
            m0 = fmaf(wv[4], s, m0);
        }
        {   // S2: floats 32..59 -> p5, p6
            float A[28];
            #pragma unroll
            for (int i = 0; i < 7; ++i)
                *reinterpret_cast<float4*>(&A[4 * i]) = M4[8 + i];
            #pragma unroll
            for (int c = 0; c < 5; ++c) {
                s = x1r[0] * A[c] + x1r[1] * A[5 + c] + x1r[2] * A[10 + c];
                m2[c] = fmaf(wv[5], s, m2[c]);
            }
            #pragma unroll
            for (int c = 0; c < 3; ++c) {
                s = x1r[0] * A[16 + c] + x1r[1] * A[19 + c] + x1r[2] * A[22 + c];
                m1[c] = fmaf(wv[6], s, m1[c]);
            }
        }
        {   // S3: floats 60..87 -> p7 (2,0,2): A[a*5+c]
            float A[28];
            #pragma unroll
            for (int i = 0; i < 7; ++i)
                *reinterpret_cast<float4*>(&A[4 * i]) = M4[15 + i];
            #pragma unroll
            for (int c = 0; c < 5; ++c) {
                s = 0.f;
                #pragma unroll
                for (int a = 0; a < 5; ++a) s = fmaf(x2r[a], A[a * 5 + c], s);
                m2[c] = fmaf(wv[7], s, m2[c]);
            }
        }
        {   // S4: floats 88..111 -> p8 (A[a*3+c]), p9 (A[16+a])
            float A[24];
            #pragma unroll
            for (int i = 0; i < 6; ++i)
                *reinterpret_cast<float4*>(&A[4 * i]) = M4[22 + i];
            #pragma unroll
            for (int c = 0; c < 3; ++c) {
                s = 0.f;
                #pragma unroll
                for (int a = 0; a < 5; ++a) s = fmaf(x2r[a], A[a * 3 + c], s);
                m1[c] = fmaf(wv[8], s, m1[c]);
            }
            s = 0.f;
            #pragma unroll
            for (int a = 0; a < 5; ++a) s = fmaf(x2r[a], A[16 + a], s);
            m0 = fmaf(wv[9], s, m0);
        }
        {   // S5: floats 112..136 -> p10 (2,2,2): A[a*5+c]
            float A[28];
            #pragma unroll
            for (int i = 0; i < 7; ++i)
                *reinterpret_cast<float4*>(&A[4 * i]) = M4[28 + i];
            #pragma unroll
            for (int c = 0; c < 5; ++c) {
                s = 0.f;
                #pragma unroll
                for (int a = 0; a < 5; ++a) s = fmaf(x2r[a], A[a * 5 + c], s);
                m2[c] = fmaf(wv[10], s, m2[c]);
            }
        }

        // coalesced channel-major atomic scatter (9 x red.f32, no staging)
        float* ob = g_outT + (size_t)dn * FEAT;
        red1(&ob[u], m0);
        #pragma unroll
        for (int a = 0; a < 3; ++a) red1(&ob[32 + a * 32 + u], m1[a]);
        #pragma unroll
        for (int a = 0; a < 5; ++a) red1(&ob[128 + a * 32 + u], m2[a]);
    }
}

// ---------------------------------------------------------------------------
extern "C" void kernel_launch(void* const* d_in, const int* in_sizes, int n_in,
                              void* d_out, int out_size) {
    const float* nodes = (const float*)d_in[0];
    const float* pos   = (const float*)d_in[1];
    const int*   src   = (const int*)d_in[2];
    const int*   dst   = (const int*)d_in[3];
    const float* w1    = (const float*)d_in[4];
    const float* b1    = (const float*)d_in[5];
    const float* w2    = (const float*)d_in[6];
    const float* b2    = (const float*)d_in[7];
    float* out = (float*)d_out;

    setup_kernel<<<SETUP_BLOCKS, 256>>>(nodes, w1, b1, w2, b2);

    cudaFuncSetAttribute(conv_kernel,
                         cudaFuncAttributeMaxDynamicSharedMemorySize, SMEM_BYTES);
    int nblocks = (N_EDGES + EPB - 1) / EPB;
    conv_kernel<<<nblocks, BLK, SMEM_BYTES>>>(pos, src, dst);

    untranspose_kernel<<<2048, 256>>>(out);
}

// round 16
// speedup vs baseline: 1.9391x; 1.0107x over previous
#include <cuda_runtime.h>
#include <cuda_bf16.h>
#include <math.h>

// ---------------------------------------------------------------------------
// Problem constants
// ---------------------------------------------------------------------------
#define N_NODES   10000
#define N_EDGES   250000
#define FF        32
#define HIDDEN    64
#define NPATHS    11
#define FEAT      288
#define NRAD      352

#define EPB       64          // edges per block
#define BLK       256         // threads per block (8 warps, 8 edges/warp)
#define M_PITCH   144         // padded pitch for M[e][elem]; path blocks 16B-aligned
#define Y_PITCH   16          // ysm pitch: 8 harmonics, [8]=1, [9..15]=0

#define RTAB_N    1024        // intervals over d in [0,4] (lerp err ~3e-5 << 1e-3)
#define RTAB_ROWS (RTAB_N + 1)
#define ROWS_PER_BLK 8
#define RTAB_BLKS ((RTAB_ROWS + ROWS_PER_BLK - 1) / ROWS_PER_BLK)   // 129

// PATHS = [(0,0,0),(0,1,1),(0,2,2),(1,0,1),(1,1,0),(1,1,2),
//          (1,2,1),(2,0,2),(2,1,1),(2,2,0),(2,2,2)]
__constant__ int c_PI[NPATHS]  = {0,0,0,1,1,1,1,2,2,2,2};
__constant__ int c_PJ[NPATHS]  = {0,1,2,0,1,1,2,0,1,2,2};
__constant__ int c_PK[NPATHS]  = {0,1,2,1,0,2,1,2,1,0,2};
// dense element-offset of path p (sizes {1,3,5,9,3,15,9,25,15,5,25} -> 115)
__constant__ int c_OFF[NPATHS]  = {0,1,4,9,18,21,36,45,70,85,90};
// padded (16B-aligned) offsets within the 144-float per-edge M vector
__constant__ int c_OFFP[NPATHS] = {0,4,8,16,28,32,48,60,88,104,112};
// PATH_W[p]/sqrt(25)
__constant__ float c_PW[NPATHS] = {
    0.11547005383792515f, 0.17320508075688773f, 0.22360679774997896f,
    0.17320508075688773f, 0.11547005383792515f, 0.22360679774997896f,
    0.17320508075688773f, 0.22360679774997896f, 0.17320508075688773f,
    0.11547005383792515f, 0.22360679774997896f};

// Transposed, pre-scaled W3J: w3jT[idx][b] = W3J[p][a, b, c] * PW[p], rows
// padded to 5 (b >= 2j+1 -> 0), idx 115..127 all-zero.
__device__ float g_w3jT[128 * 5];
// Interleaved radial*cutoff table: g_rtab2[i*NRAD+r] = {rad(d_i)[r], rad(d_{i+1})[r]}
__device__ float2 g_rtab2[RTAB_N * NRAD];        // 2.9 MB static scratch
// Channel-major repacked node features
__device__ float g_nodesT[N_NODES * FEAT];       // 11.5 MB static scratch
// Channel-major output accumulator (transposed back at the end)
__device__ __align__(16) float g_outT[N_NODES * FEAT];

// ---------------------------------------------------------------------------
// Fused setup kernel (2048 blocks x 256 threads):
//   - grid-stride zero of g_outT
//   - grid-stride channel-major node repack (coalesced READS, scattered writes)
//   - blocks [RTAB_BLKS, RTAB_BLKS+NPATHS): W3J table (sparse scatter)
//   - blocks [0, RTAB_BLKS): 8 rows of the radial*cutoff table (w2 reused 8x)
// ---------------------------------------------------------------------------
__device__ __forceinline__ float ffact(int n) {
    float r = 1.0f;
    for (int i = 2; i <= n; ++i) r *= (float)i;
    return r;
}

__device__ float su2_cg_f(int j1, int j2, int j3, int m1, int m2, int m3) {
    if (m1 + m2 != m3) return 0.0f;
    float pref = sqrtf((2.0f * j3 + 1.0f) * ffact(j1 + j2 - j3) * ffact(j1 - j2 + j3) *
                       ffact(-j1 + j2 + j3) / ffact(j1 + j2 + j3 + 1));
    pref *= sqrtf(ffact(j3 + m3) * ffact(j3 - m3) * ffact(j1 - m1) * ffact(j1 + m1) *
                  ffact(j2 - m2) * ffact(j2 + m2));
    float s = 0.0f;
    for (int k = 0; k <= j1 + j2 - j3; ++k) {
        int e1 = j1 + j2 - j3 - k, e2 = j1 - m1 - k, e3 = j2 + m2 - k;
        int e4 = j3 - j2 + m1 + k, e5 = j3 - j1 - m2 + k;
        if (e1 < 0 || e2 < 0 || e3 < 0 || e4 < 0 || e5 < 0) continue;
        float term = 1.0f / (ffact(k) * ffact(e1) * ffact(e2) * ffact(e3) *
                             ffact(e4) * ffact(e5));
        s += (k & 1) ? -term : term;
    }
    return pref * s;
}

// nonzeros of row r of q(l), including the (-1j)^l prefactor. Returns count (1 or 2).
__device__ __forceinline__ int qrow(int l, int r, int* col, float* re, float* im) {
    const float is2 = 0.70710678118654752440f;
    int m = r - l;
    int cnt;
    float a[2], b[2];
    if (m < 0) {
        col[0] = l - m; a[0] = is2;  b[0] = 0.f;
        col[1] = l + m; a[1] = 0.f;  b[1] = -is2;
        cnt = 2;
    } else if (m == 0) {
        col[0] = l; a[0] = 1.f; b[0] = 0.f;
        cnt = 1;
    } else {
        float sg = (m & 1) ? -1.f : 1.f;
        col[0] = l + m; a[0] = sg * is2; b[0] = 0.f;
        col[1] = l - m; a[1] = 0.f;      b[1] = sg * is2;
        cnt = 2;
    }
    #pragma unroll
    for (int q = 0; q < 2; ++q) {
        if (q >= cnt) break;
        float A = a[q], B = b[q];
        if (l == 1) { float tA = B, tB = -A; A = tA; B = tB; }   // *(-i)
        else if (l == 2) { A = -A; B = -B; }                     // *(-1)
        re[q] = A; im[q] = B;
    }
    return cnt;
}

#define SETUP_BLOCKS 2048

__global__ void __launch_bounds__(256) setup_kernel(
    const float* __restrict__ nodes,
    const float* __restrict__ w1, const float* __restrict__ b1,
    const float* __restrict__ w2, const float* __restrict__ b2)
{
    int t = threadIdx.x;

    // ---- part 1: grid-stride zero of the transposed accumulator (float4) ----
    {
        float4* o4 = (float4*)g_outT;
        float4 z = make_float4(0.f, 0.f, 0.f, 0.f);
        for (int i = blockIdx.x * blockDim.x + t; i < N_NODES * FEAT / 4;
             i += gridDim.x * blockDim.x)
            o4[i] = z;
    }
    // ---- part 2: node repack, source-linear (coalesced LDG, scattered STG) ----
    for (int idx = blockIdx.x * blockDim.x + t; idx < N_NODES * FEAT;
         idx += gridDim.x * blockDim.x) {
        int n = idx / FEAT, r = idx - n * FEAT;
        float v = nodes[idx];
        int rT;
        if (r < 32) {
            rT = r;                                  // x0: identical layout
        } else if (r < 128) {
            int rr = r - 32;
            int uu = rr / 3, a = rr - uu * 3;        // src is [u][a]
            rT = 32 + a * 32 + uu;                   // dst is [a][u]
        } else {
            int rr = r - 128;
            int uu = rr / 5, a = rr - uu * 5;
            rT = 128 + a * 32 + uu;
        }
        g_nodesT[n * FEAT + rT] = v;
    }

    // ---- part 3: W3J (blocks RTAB_BLKS .. RTAB_BLKS+NPATHS-1) ----
    __shared__ float C[125], Wre[125], Wim[125];
    __shared__ float sel[2];
    if (blockIdx.x >= RTAB_BLKS && blockIdx.x < RTAB_BLKS + NPATHS) {
        int p = blockIdx.x - RTAB_BLKS;
        int l1 = c_PI[p], l2 = c_PJ[p], l3 = c_PK[p];
        int d1 = 2 * l1 + 1, d2 = 2 * l2 + 1, d3 = 2 * l3 + 1;
        int n = d1 * d2 * d3;

        for (int idx = t; idx < n; idx += blockDim.x) {
            int i = idx / (d2 * d3), k = (idx / d3) % d2, m = idx % d3;
            C[idx] = su2_cg_f(l1, l2, l3, i - l1, k - l2, m - l3);
            Wre[idx] = 0.f; Wim[idx] = 0.f;
        }
        __syncthreads();

        // sparse scatter: each nonzero C entry contributes <=8 outputs
        for (int idx = t; idx < n; idx += blockDim.x) {
            float cc = C[idx];
            if (cc == 0.f) continue;
            int i = idx / (d2 * d3), k = (idx / d3) % d2, m = idx % d3;
            int   c1[2], c2[2], c3[2];
            float a1[2], b1r[2], a2[2], b2r[2], a3[2], b3r[2];
            int n1 = qrow(l1, i, c1, a1, b1r);
            int n2 = qrow(l2, k, c2, a2, b2r);
            int n3 = qrow(l3, m, c3, a3, b3r);
            for (int x = 0; x < n1; ++x)
                for (int y = 0; y < n2; ++y) {
                    float pr = a1[x] * a2[y] - b1r[x] * b2r[y];
                    float pi = a1[x] * b2r[y] + b1r[x] * a2[y];
                    for (int z = 0; z < n3; ++z) {
                        float rr = pr * a3[z] + pi * b3r[z];   // * conj(q3)
                        float ri = pi * a3[z] - pr * b3r[z];
                        int o = (c1[x] * d2 + c2[y]) * d3 + c3[z];
                        atomicAdd(&Wre[o], cc * rr);
                        atomicAdd(&Wim[o], cc * ri);
                    }
                }
        }
        __syncthreads();

        if (t == 0) {
            float nr = 0.0f, ni = 0.0f;
            for (int idx = 0; idx < n; ++idx) {
                nr += Wre[idx] * Wre[idx];
                ni += Wim[idx] * Wim[idx];
            }
            nr = sqrtf(nr); ni = sqrtf(ni);
            sel[0] = (nr >= ni) ? 1.0f : 0.0f;
            sel[1] = (nr >= ni) ? nr : ni;
        }
        __syncthreads();

        bool useRe = sel[0] > 0.5f;
        float scl = c_PW[p] / sel[1];
        const float* W = useRe ? Wre : Wim;

        int off = c_OFF[p];
        int nr5 = d1 * d3 * 5;
        for (int rb = t; rb < nr5; rb += blockDim.x) {
            int r = rb / 5, b = rb - r * 5;
            int a = r / d3, c = r - a * d3;
            float v = (b < d2) ? W[(a * d2 + b) * d3 + c] * scl : 0.f;
            g_w3jT[(off + r) * 5 + b] = v;
        }
        if (p == 0)
            for (int z = t; z < 65; z += blockDim.x) g_w3jT[575 + z] = 0.f;
    }

    // ---- part 4: radial*cutoff table, 8 rows per block (blocks < RTAB_BLKS) ----
    __shared__ float h[ROWS_PER_BLK][HIDDEN];
    __shared__ float cutf[ROWS_PER_BLK];
    if (blockIdx.x < RTAB_BLKS) {
        int i0 = blockIdx.x * ROWS_PER_BLK;

        // hidden activations for the 8 rows (512 values, 256 threads x2)
        for (int z = t; z < ROWS_PER_BLK * HIDDEN; z += 256) {
            int row = z >> 6, l64 = z & 63;
            int i = i0 + row;
            if (i < RTAB_ROWS) {
                float d = (float)i * (4.0f / (float)RTAB_N);
                float tt = d * 0.2f;                       // d / BESSEL_END
                float a = b1[l64];
                if (tt > 0.0f && tt < 1.0f) {
                    float cc = 0.6324555320336759f / tt;   // sqrt(2/5)/t
                    #pragma unroll
                    for (int n = 1; n <= 8; ++n) {
                        float bv = cc * sinf((float)n * 3.14159265358979323846f * tt);
                        a = fmaf(bv, w1[(n - 1) * HIDDEN + l64], a);
                    }
                }
                h[row][l64] = a / (1.0f + __expf(-a));     // silu
            } else {
                h[row][l64] = 0.f;
            }
        }
        if (t < ROWS_PER_BLK) {
            int i = i0 + t;
            float cv = 0.f;
            if (i < RTAB_ROWS) {
                float d = (float)i * (4.0f / (float)RTAB_N);
                if (d < 4.0f) {
                    float uu = d * 0.25f;
                    float u2 = uu * uu, u4 = u2 * u2, u5 = u4 * uu;
                    cv = 1.0f - 6.0f * u5 + 5.0f * u5 * uu;
                }
            }
            cutf[t] = cv;
        }
        __syncthreads();

        float* tab = reinterpret_cast<float*>(g_rtab2);
        for (int r = t; r < NRAD; r += 256) {
            float acc[ROWS_PER_BLK];
            float bb = b2[r];
            #pragma unroll
            for (int row = 0; row < ROWS_PER_BLK; ++row) acc[row] = bb;
            #pragma unroll 4
            for (int j = 0; j < HIDDEN; ++j) {
                float w = w2[j * NRAD + r];
                #pragma unroll
                for (int row = 0; row < ROWS_PER_BLK; ++row)
                    acc[row] = fmaf(h[row][j], w, acc[row]);
            }
            #pragma unroll
            for (int row = 0; row < ROWS_PER_BLK; ++row) {
                int i = i0 + row;
                if (i < RTAB_ROWS) {
                    float s = acc[row] * cutf[row];
                    if (i < RTAB_N) tab[2 * (i * NRAD + r)] = s;            // .x row i
                    if (i > 0)      tab[2 * ((i - 1) * NRAD + r) + 1] = s;  // .y row i-1
                }
            }
        }
    }
}

// ---------------------------------------------------------------------------
// Final transpose: out (reference layout) <- g_outT (channel-major)
// ---------------------------------------------------------------------------
__global__ void __launch_bounds__(256) untranspose_kernel(float* __restrict__ out) {
    for (int idx = blockIdx.x * 256 + threadIdx.x; idx < N_NODES * FEAT;
         idx += gridDim.x * 256) {
        int n = idx / FEAT, r = idx - n * FEAT;
        int rT;
        if (r < 32) {
            rT = r;
        } else if (r < 128) {
            int rr = r - 32;
            int uu = rr / 3, a = rr - uu * 3;
            rT = 32 + a * 32 + uu;
        } else {
            int rr = r - 128;
            int uu = rr / 5, a = rr - uu * 5;
            rT = 128 + a * 32 + uu;
        }
        out[idx] = g_outT[n * FEAT + rT];
    }
}

// ---------------------------------------------------------------------------
__device__ __forceinline__ void red1(float* p, float v) {
    asm volatile("red.global.add.f32 [%0], %1;" :: "l"(p), "f"(v) : "memory");
}

// dynamic smem layout (float slots); MSM is 16B-aligned
#define SM_MSM   0                        // 144*64 = 9216
#define SM_YSM   9216                     // 16*64 = 1024
#define SM_W3JT  10240                    // 640
#define SM_CUT   (SM_W3JT + 640)          // 64
#define SM_DIST  (SM_CUT + 64)            // 64
#define SM_SRC   (SM_DIST + 64)           // 64 (int)
#define SM_DST   (SM_SRC + 64)            // 64 (int)
#define SM_TOTALF (SM_DST + 64)           // 11136 floats
#define SMEM_BYTES (SM_TOTALF * 4)        // 44544 B

__global__ void __launch_bounds__(BLK, 3) conv_kernel(
    const float* __restrict__ pos,
    const int* __restrict__ src, const int* __restrict__ dst)
{
    extern __shared__ float smf[];
    float* Msm   = smf + SM_MSM;
    float* ysm   = smf + SM_YSM;
    float* w3jTs = smf + SM_W3JT;
    float* cutsm = smf + SM_CUT;
    float* distsm= smf + SM_DIST;
    int*   srcsm = (int*)(smf + SM_SRC);
    int*   dstsm = (int*)(smf + SM_DST);

    const int t  = threadIdx.x;
    const int u  = t & 31;       // lane == channel
    const int wr = t >> 5;       // warp 0..7 owns edges 8*wr .. 8*wr+7

    // stage w3jT table into smem (640 floats)
    #pragma unroll
    for (int r = 0; r < 3; ++r) {
        int idx = r * BLK + t;
        if (idx < 640) w3jTs[idx] = g_w3jT[idx];
    }

    // ================= Phase A: per-edge geometry (threads 0..63) ==========
    if (t < EPB) {
        int eg = blockIdx.x * EPB + t;
        float cut = 0.f, ux = 0.f, uy = 0.f, uz = 0.f, d = 0.f;
        int sn = 0, dn = 0;
        if (eg < N_EDGES) {
            sn = src[eg]; dn = dst[eg];
            float px = pos[3 * sn]     - pos[3 * dn];
            float py = pos[3 * sn + 1] - pos[3 * dn + 1];
            float pz = pos[3 * sn + 2] - pos[3 * dn + 2];
            d = sqrtf(px * px + py * py + pz * pz);
            float rin = 1.0f / fmaxf(d, 1e-12f);
            ux = px * rin; uy = py * rin; uz = pz * rin;
            if (d < 4.0f) cut = 1.0f;            // live-edge flag
        }
        cutsm[t] = cut;
        distsm[t] = d;
        srcsm[t] = sn; dstsm[t] = dn;
        const float s3 = 1.7320508075688772f, s15 = 3.872983346207417f;
        const float s5h = 1.118033988749895f, s15h = 1.9364916731037085f;
        float* ye = ysm + t * Y_PITCH;
        ye[0] = s3 * uy;
        ye[1] = s3 * uz;
        ye[2] = s3 * ux;
        ye[3] = s15 * ux * uy;
        ye[4] = s15 * uy * uz;
        ye[5] = s5h * (3.0f * uz * uz - 1.0f);
        ye[6] = s15 * ux * uz;
        ye[7] = s15h * (ux * ux - uy * uy);
        ye[8] = 1.0f;
        #pragma unroll
        for (int z = 9; z < Y_PITCH; ++z) ye[z] = 0.f;
    }
    __syncthreads();

    // ================= Phase D: per-edge M matrices ========================
    int   md_yoff[4], md_pos[4], md_row[4];
    #pragma unroll
    for (int g = 0; g < 4; ++g) {
        int idx = g * 32 + u;
        bool v = (idx < 115);
        int p = 10;
        if (v) { while (c_OFF[p] > idx) --p; } else { p = 0; }
        int r  = idx - c_OFF[p];
        int wk = 2 * c_PK[p] + 1;
        int a  = r / wk;
        int c  = r - a * wk;
        int jj = c_PJ[p];
        md_yoff[g] = (jj == 0) ? 8 : ((jj == 1) ? 0 : 3);
        md_pos[g]  = v ? (c_OFFP[p] + r) : 143;       // invalid -> pad slot
        md_row[g]  = idx * 5;
    }
    for (int q = 0; q < 8; ++q) {
        int e = 8 * wr + q;
        if (cutsm[e] == 0.f) continue;      // dead edge (warp-uniform)
        const float* ye = ysm + e * Y_PITCH;
        #pragma unroll
        for (int g = 0; g < 4; ++g) {
            const float* wrow = w3jTs + md_row[g];
            const float* yb = ye + md_yoff[g];
            float a = wrow[0] * yb[0];
            #pragma unroll
            for (int b = 1; b < 5; ++b) a = fmaf(wrow[b], yb[b], a);
            Msm[e * M_PITCH + md_pos[g]] = a;
        }
    }
    __syncwarp();

    // ================= Phase E: radial lookup + tensor product + scatter ===
    #pragma unroll
    for (int q = 0; q < 8; ++q) {
        int e = 8 * wr + q;
        if (cutsm[e] == 0.f) continue;      // warp-uniform skip
        int sn = srcsm[e], dn = dstsm[e];

        // radial*cutoff via interleaved-table lerp (d < 4 guaranteed here)
        float x = distsm[e] * ((float)RTAB_N * 0.25f);
        int i0 = (int)x;
        i0 = (i0 > RTAB_N - 1) ? (RTAB_N - 1) : i0;
        float f = x - (float)i0;
        const float2* T = g_rtab2 + i0 * NRAD + u;
        float wv[NPATHS];
        #pragma unroll
        for (int p = 0; p < NPATHS; ++p) {
            float2 ab = T[p * 32];
            wv[p] = fmaf(ab.y - ab.x, f, ab.x);
        }

        // coalesced channel-major node gather
        const float* xb = g_nodesT + (size_t)sn * FEAT;
        float x0r = xb[u];
        float x1r[3], x2r[5];
        #pragma unroll
        for (int a = 0; a < 3; ++a) x1r[a] = xb[32 + a * 32 + u];
        #pragma unroll
        for (int a = 0; a < 5; ++a) x2r[a] = xb[128 + a * 32 + u];

        const float4* M4 = reinterpret_cast<const float4*>(Msm + e * M_PITCH);
        float m0 = 0.f, m1[3] = {0.f, 0.f, 0.f}, m2[5] = {0.f, 0.f, 0.f, 0.f, 0.f};
        float s;

        {   // S1: floats 0..31 -> p0..p4
            float A[32];
            #pragma unroll
            for (int i = 0; i < 8; ++i)
                *reinterpret_cast<float4*>(&A[4 * i]) = M4[i];
            m0 = fmaf(wv[0], x0r * A[0], m0);
            #pragma unroll
            for (int c = 0; c < 3; ++c) m1[c] = fmaf(wv[1], x0r * A[4 + c], m1[c]);
            #pragma unroll
            for (int c = 0; c < 5; ++c) m2[c] = fmaf(wv[2], x0r * A[8 + c], m2[c]);
            #pragma unroll
            for (int c = 0; c < 3; ++c) {
                s = x1r[0] * A[16 + c] + x1r[1] * A[19 + c] + x1r[2] * A[22 + c];
                m1[c] = fmaf(wv[3], s, m1[c]);
            }
            s = x1r[0] * A[28] + x1r[1] * A[29] + x1r[2] * A[30];
            m0 = fmaf(wv[4], s, m0);
        }
        {   // S2: floats 32..59 -> p5, p6
            float A[28];
            #pragma unroll
            for (int i = 0; i < 7; ++i)
                *reinterpret_cast<float4*>(&A[4 * i]) = M4[8 + i];
            #pragma unroll
            for (int c = 0; c < 5; ++c) {
                s = x1r[0] * A[c] + x1r[1] * A[5 + c] + x1r[2] * A[10 + c];
                m2[c] = fmaf(wv[5], s, m2[c]);
            }
            #pragma unroll
            for (int c = 0; c < 3; ++c) {
                s = x1r[0] * A[16 + c] + x1r[1] * A[19 + c] + x1r[2] * A[22 + c];
                m1[c] = fmaf(wv[6], s, m1[c]);
            }
        }
        {   // S3: floats 60..87 -> p7 (2,0,2): A[a*5+c]
            float A[28];
            #pragma unroll
            for (int i = 0; i < 7; ++i)
                *reinterpret_cast<float4*>(&A[4 * i]) = M4[15 + i];
            #pragma unroll
            for (int c = 0; c < 5; ++c) {
                s = 0.f;
                #pragma unroll
                for (int a = 0; a < 5; ++a) s = fmaf(x2r[a], A[a * 5 + c], s);
                m2[c] = fmaf(wv[7], s, m2[c]);
            }
        }
        {   // S4: floats 88..111 -> p8 (A[a*3+c]), p9 (A[16+a])
            float A[24];
            #pragma unroll
            for (int i = 0; i < 6; ++i)
                *reinterpret_cast<float4*>(&A[4 * i]) = M4[22 + i];
            #pragma unroll
            for (int c = 0; c < 3; ++c) {
                s = 0.f;
                #pragma unroll
                for (int a = 0; a < 5; ++a) s = fmaf(x2r[a], A[a * 3 + c], s);
                m1[c] = fmaf(wv[8], s, m1[c]);
            }
            s = 0.f;
            #pragma unroll
            for (int a = 0; a < 5; ++a) s = fmaf(x2r[a], A[16 + a], s);
            m0 = fmaf(wv[9], s, m0);
        }
        {   // S5: floats 112..136 -> p10 (2,2,2): A[a*5+c]
            float A[28];
            #pragma unroll
            for (int i = 0; i < 7; ++i)
                *reinterpret_cast<float4*>(&A[4 * i]) = M4[28 + i];
            #pragma unroll
            for (int c = 0; c < 5; ++c) {
                s = 0.f;
                #pragma unroll
                for (int a = 0; a < 5; ++a) s = fmaf(x2r[a], A[a * 5 + c], s);
                m2[c] = fmaf(wv[10], s, m2[c]);
            }
        }

        // coalesced channel-major atomic scatter (9 x red.f32, no staging)
        float* ob = g_outT + (size_t)dn * FEAT;
        red1(&ob[u], m0);
        #pragma unroll
        for (int a = 0; a < 3; ++a) red1(&ob[32 + a * 32 + u], m1[a]);
        #pragma unroll
        for (int a = 0; a < 5; ++a) red1(&ob[128 + a * 32 + u], m2[a]);
    }
}

// ---------------------------------------------------------------------------
extern "C" void kernel_launch(void* const* d_in, const int* in_sizes, int n_in,
                              void* d_out, int out_size) {
    const float* nodes = (const float*)d_in[0];
    const float* pos   = (const float*)d_in[1];
    const int*   src   = (const int*)d_in[2];
    const int*   dst   = (const int*)d_in[3];
    const float* w1    = (const float*)d_in[4];
    const float* b1    = (const float*)d_in[5];
    const float* w2    = (const float*)d_in[6];
    const float* b2    = (const float*)d_in[7];
    float* out = (float*)d_out;

    setup_kernel<<<SETUP_BLOCKS, 256>>>(nodes, w1, b1, w2, b2);

    cudaFuncSetAttribute(conv_kernel,
                         cudaFuncAttributeMaxDynamicSharedMemorySize, SMEM_BYTES);
    int nblocks = (N_EDGES + EPB - 1) / EPB;
    conv_kernel<<<nblocks, BLK, SMEM_BYTES>>>(pos, src, dst);

    untranspose_kernel<<<2048, 256>>>(out);
}

// round 17
// speedup vs baseline: 2.0476x; 1.0560x over previous
#include <cuda_runtime.h>
#include <cuda_bf16.h>
#include <cuda_fp16.h>
#include <math.h>

// ---------------------------------------------------------------------------
// Problem constants
// ---------------------------------------------------------------------------
#define N_NODES   10000
#define N_EDGES   250000
#define FF        32
#define HIDDEN    64
#define NPATHS    11
#define FEAT      288
#define NRAD      352

#define EPB       64          // edges per block
#define BLK       256         // threads per block (8 warps, 8 edges/warp)
#define M_PITCH   144         // padded pitch for M[e][elem]; path blocks 16B-aligned
#define Y_PITCH   16          // ysm pitch: 8 harmonics, [8]=1, [9..15]=0

#define RTAB_N    1024        // intervals over d in [0,4] (lerp err ~3e-5 << 1e-3)
#define RTAB_ROWS (RTAB_N + 1)
#define ROWS_PER_BLK 8
#define RTAB_BLKS ((RTAB_ROWS + ROWS_PER_BLK - 1) / ROWS_PER_BLK)   // 129

// PATHS = [(0,0,0),(0,1,1),(0,2,2),(1,0,1),(1,1,0),(1,1,2),
//          (1,2,1),(2,0,2),(2,1,1),(2,2,0),(2,2,2)]
__constant__ int c_PI[NPATHS]  = {0,0,0,1,1,1,1,2,2,2,2};
__constant__ int c_PJ[NPATHS]  = {0,1,2,0,1,1,2,0,1,2,2};
__constant__ int c_PK[NPATHS]  = {0,1,2,1,0,2,1,2,1,0,2};
// dense element-offset of path p (sizes {1,3,5,9,3,15,9,25,15,5,25} -> 115)
__constant__ int c_OFF[NPATHS]  = {0,1,4,9,18,21,36,45,70,85,90};
// padded (16B-aligned) offsets within the 144-float per-edge M vector
__constant__ int c_OFFP[NPATHS] = {0,4,8,16,28,32,48,60,88,104,112};
// PATH_W[p]/sqrt(25)
__constant__ float c_PW[NPATHS] = {
    0.11547005383792515f, 0.17320508075688773f, 0.22360679774997896f,
    0.17320508075688773f, 0.11547005383792515f, 0.22360679774997896f,
    0.17320508075688773f, 0.22360679774997896f, 0.17320508075688773f,
    0.11547005383792515f, 0.22360679774997896f};

// Transposed, pre-scaled W3J: w3jT[idx][b] = W3J[p][a, b, c] * PW[p], rows
// padded to 5 (b >= 2j+1 -> 0), idx 115..127 all-zero.
__device__ float g_w3jT[128 * 5];
// Interleaved fp16 radial*cutoff table:
//   g_rtab_h[i*NRAD+r] = {rad(d_i)[r], rad(d_{i+1})[r]}  (half2)
__device__ __half2 g_rtab_h[RTAB_N * NRAD];      // 1.45 MB static scratch
// Channel-major repacked node features
__device__ float g_nodesT[N_NODES * FEAT];       // 11.5 MB static scratch
// Channel-major output accumulator. Zero-initialized at module load;
// untranspose_kernel re-zeroes it after reading, so every call starts zeroed.
__device__ __align__(16) float g_outT[N_NODES * FEAT];

// ---------------------------------------------------------------------------
// Fused setup kernel (2048 blocks x 256 threads):
//   - grid-stride channel-major node repack (coalesced READS, scattered writes)
//   - blocks [RTAB_BLKS, RTAB_BLKS+NPATHS): W3J table (sparse scatter)
//   - blocks [0, RTAB_BLKS): 8 rows of the radial*cutoff table (w2 reused 8x)
// ---------------------------------------------------------------------------
__device__ __forceinline__ float ffact(int n) {
    float r = 1.0f;
    for (int i = 2; i <= n; ++i) r *= (float)i;
    return r;
}

__device__ float su2_cg_f(int j1, int j2, int j3, int m1, int m2, int m3) {
    if (m1 + m2 != m3) return 0.0f;
    float pref = sqrtf((2.0f * j3 + 1.0f) * ffact(j1 + j2 - j3) * ffact(j1 - j2 + j3) *
                       ffact(-j1 + j2 + j3) / ffact(j1 + j2 + j3 + 1));
    pref *= sqrtf(ffact(j3 + m3) * ffact(j3 - m3) * ffact(j1 - m1) * ffact(j1 + m1) *
                  ffact(j2 - m2) * ffact(j2 + m2));
    float s = 0.0f;
    for (int k = 0; k <= j1 + j2 - j3; ++k) {
        int e1 = j1 + j2 - j3 - k, e2 = j1 - m1 - k, e3 = j2 + m2 - k;
        int e4 = j3 - j2 + m1 + k, e5 = j3 - j1 - m2 + k;
        if (e1 < 0 || e2 < 0 || e3 < 0 || e4 < 0 || e5 < 0) continue;
        float term = 1.0f / (ffact(k) * ffact(e1) * ffact(e2) * ffact(e3) *
                             ffact(e4) * ffact(e5));
        s += (k & 1) ? -term : term;
    }
    return pref * s;
}

// nonzeros of row r of q(l), including the (-1j)^l prefactor. Returns count (1 or 2).
__device__ __forceinline__ int qrow(int l, int r, int* col, float* re, float* im) {
    const float is2 = 0.70710678118654752440f;
    int m = r - l;
    int cnt;
    float a[2], b[2];
    if (m < 0) {
        col[0] = l - m; a[0] = is2;  b[0] = 0.f;
        col[1] = l + m; a[1] = 0.f;  b[1] = -is2;
        cnt = 2;
    } else if (m == 0) {
        col[0] = l; a[0] = 1.f; b[0] = 0.f;
        cnt = 1;
    } else {
        float sg = (m & 1) ? -1.f : 1.f;
        col[0] = l + m; a[0] = sg * is2; b[0] = 0.f;
        col[1] = l - m; a[1] = 0.f;      b[1] = sg * is2;
        cnt = 2;
    }
    #pragma unroll
    for (int q = 0; q < 2; ++q) {
        if (q >= cnt) break;
        float A = a[q], B = b[q];
        if (l == 1) { float tA = B, tB = -A; A = tA; B = tB; }   // *(-i)
        else if (l == 2) { A = -A; B = -B; }                     // *(-1)
        re[q] = A; im[q] = B;
    }
    return cnt;
}

#define SETUP_BLOCKS 2048

__global__ void __launch_bounds__(256) setup_kernel(
    const float* __restrict__ nodes,
    const float* __restrict__ w1, const float* __restrict__ b1,
    const float* __restrict__ w2, const float* __restrict__ b2)
{
    int t = threadIdx.x;

    // ---- part 1: node repack, source-linear (coalesced LDG, scattered STG) ----
    for (int idx = blockIdx.x * blockDim.x + t; idx < N_NODES * FEAT;
         idx += gridDim.x * blockDim.x) {
        int n = idx / FEAT, r = idx - n * FEAT;
        float v = nodes[idx];
        int rT;
        if (r < 32) {
            rT = r;                                  // x0: identical layout
        } else if (r < 128) {
            int rr = r - 32;
            int uu = rr / 3, a = rr - uu * 3;        // src is [u][a]
            rT = 32 + a * 32 + uu;                   // dst is [a][u]
        } else {
            int rr = r - 128;
            int uu = rr / 5, a = rr - uu * 5;
            rT = 128 + a * 32 + uu;
        }
        g_nodesT[n * FEAT + rT] = v;
    }

    // ---- part 2: W3J (blocks RTAB_BLKS .. RTAB_BLKS+NPATHS-1) ----
    __shared__ float C[125], Wre[125], Wim[125];
    __shared__ float sel[2];
    if (blockIdx.x >= RTAB_BLKS && blockIdx.x < RTAB_BLKS + NPATHS) {
        int p = blockIdx.x - RTAB_BLKS;
        int l1 = c_PI[p], l2 = c_PJ[p], l3 = c_PK[p];
        int d1 = 2 * l1 + 1, d2 = 2 * l2 + 1, d3 = 2 * l3 + 1;
        int n = d1 * d2 * d3;

        for (int idx = t; idx < n; idx += blockDim.x) {
            int i = idx / (d2 * d3), k = (idx / d3) % d2, m = idx % d3;
            C[idx] = su2_cg_f(l1, l2, l3, i - l1, k - l2, m - l3);
            Wre[idx] = 0.f; Wim[idx] = 0.f;
        }
        __syncthreads();

        // sparse scatter: each nonzero C entry contributes <=8 outputs
        for (int idx = t; idx < n; idx += blockDim.x) {
            float cc = C[idx];
            if (cc == 0.f) continue;
            int i = idx / (d2 * d3), k = (idx / d3) % d2, m = idx % d3;
            int   c1[2], c2[2], c3[2];
            float a1[2], b1r[2], a2[2], b2r[2], a3[2], b3r[2];
            int n1 = qrow(l1, i, c1, a1, b1r);
            int n2 = qrow(l2, k, c2, a2, b2r);
            int n3 = qrow(l3, m, c3, a3, b3r);
            for (int x = 0; x < n1; ++x)
                for (int y = 0; y < n2; ++y) {
                    float pr = a1[x] * a2[y] - b1r[x] * b2r[y];
                    float pi = a1[x] * b2r[y] + b1r[x] * a2[y];
                    for (int z = 0; z < n3; ++z) {
                        float rr = pr * a3[z] + pi * b3r[z];   // * conj(q3)
                        float ri = pi * a3[z] - pr * b3r[z];
                        int o = (c1[x] * d2 + c2[y]) * d3 + c3[z];
                        atomicAdd(&Wre[o], cc * rr);
                        atomicAdd(&Wim[o], cc * ri);
                    }
                }
        }
        __syncthreads();

        if (t == 0) {
            float nr = 0.0f, ni = 0.0f;
            for (int idx = 0; idx < n; ++idx) {
                nr += Wre[idx] * Wre[idx];
                ni += Wim[idx] * Wim[idx];
            }
            nr = sqrtf(nr); ni = sqrtf(ni);
            sel[0] = (nr >= ni) ? 1.0f : 0.0f;
            sel[1] = (nr >= ni) ? nr : ni;
        }
        __syncthreads();

        bool useRe = sel[0] > 0.5f;
        float scl = c_PW[p] / sel[1];
        const float* W = useRe ? Wre : Wim;

        int off = c_OFF[p];
        int nr5 = d1 * d3 * 5;
        for (int rb = t; rb < nr5; rb += blockDim.x) {
            int r = rb / 5, b = rb - r * 5;
            int a = r / d3, c = r - a * d3;
            float v = (b < d2) ? W[(a * d2 + b) * d3 + c] * scl : 0.f;
            g_w3jT[(off + r) * 5 + b] = v;
        }
        if (p == 0)
            for (int z = t; z < 65; z += blockDim.x) g_w3jT[575 + z] = 0.f;
    }

    // ---- part 3: fp16 radial*cutoff table, 8 rows per block ----
    __shared__ float h[ROWS_PER_BLK][HIDDEN];
    __shared__ float cutf[ROWS_PER_BLK];
    if (blockIdx.x < RTAB_BLKS) {
        int i0 = blockIdx.x * ROWS_PER_BLK;

        // hidden activations for the 8 rows (512 values, 256 threads x2)
        for (int z = t; z < ROWS_PER_BLK * HIDDEN; z += 256) {
            int row = z >> 6, l64 = z & 63;
            int i = i0 + row;
            if (i < RTAB_ROWS) {
                float d = (float)i * (4.0f / (float)RTAB_N);
                float tt = d * 0.2f;                       // d / BESSEL_END
                float a = b1[l64];
                if (tt > 0.0f && tt < 1.0f) {
                    float cc = 0.6324555320336759f / tt;   // sqrt(2/5)/t
                    #pragma unroll
                    for (int n = 1; n <= 8; ++n) {
                        float bv = cc * sinf((float)n * 3.14159265358979323846f * tt);
                        a = fmaf(bv, w1[(n - 1) * HIDDEN + l64], a);
                    }
                }
                h[row][l64] = a / (1.0f + __expf(-a));     // silu
            } else {
                h[row][l64] = 0.f;
            }
        }
        if (t < ROWS_PER_BLK) {
            int i = i0 + t;
            float cv = 0.f;
            if (i < RTAB_ROWS) {
                float d = (float)i * (4.0f / (float)RTAB_N);
                if (d < 4.0f) {
                    float uu = d * 0.25f;
                    float u2 = uu * uu, u4 = u2 * u2, u5 = u4 * uu;
                    cv = 1.0f - 6.0f * u5 + 5.0f * u5 * uu;
                }
            }
            cutf[t] = cv;
        }
        __syncthreads();

        __half* tabh = reinterpret_cast<__half*>(g_rtab_h);
        for (int r = t; r < NRAD; r += 256) {
            float acc[ROWS_PER_BLK];
            float bb = b2[r];
            #pragma unroll
            for (int row = 0; row < ROWS_PER_BLK; ++row) acc[row] = bb;
            #pragma unroll 4
            for (int j = 0; j < HIDDEN; ++j) {
                float w = w2[j * NRAD + r];
                #pragma unroll
                for (int row = 0; row < ROWS_PER_BLK; ++row)
                    acc[row] = fmaf(h[row][j], w, acc[row]);
            }
            #pragma unroll
            for (int row = 0; row < ROWS_PER_BLK; ++row) {
                int i = i0 + row;
                if (i < RTAB_ROWS) {
                    __half s = __float2half(acc[row] * cutf[row]);
                    if (i < RTAB_N) tabh[2 * (i * NRAD + r)] = s;            // .x row i
                    if (i > 0)      tabh[2 * ((i - 1) * NRAD + r) + 1] = s;  // .y row i-1
                }
            }
        }
    }
}

// ---------------------------------------------------------------------------
// Final transpose: out (reference layout) <- g_outT (channel-major).
// Re-zeroes g_outT after reading so the next call starts from zero.
// ---------------------------------------------------------------------------
__global__ void __launch_bounds__(256) untranspose_kernel(float* __restrict__ out) {
    for (int idx = blockIdx.x * 256 + threadIdx.x; idx < N_NODES * FEAT;
         idx += gridDim.x * 256) {
        int n = idx / FEAT, r = idx - n * FEAT;
        int rT;
        if (r < 32) {
            rT = r;
        } else if (r < 128) {
            int rr = r - 32;
            int uu = rr / 3, a = rr - uu * 3;
            rT = 32 + a * 32 + uu;
        } else {
            int rr = r - 128;
            int uu = rr / 5, a = rr - uu * 5;
            rT = 128 + a * 32 + uu;
        }
        float* p = g_outT + n * FEAT + rT;
        out[idx] = *p;
        *p = 0.0f;                    // leave accumulator zeroed for next call
    }
}

// ---------------------------------------------------------------------------
__device__ __forceinline__ void red1(float* p, float v) {
    asm volatile("red.global.add.f32 [%0], %1;" :: "l"(p), "f"(v) : "memory");
}

// dynamic smem layout (float slots); MSM is 16B-aligned
#define SM_MSM   0                        // 144*64 = 9216
#define SM_YSM   9216                     // 16*64 = 1024
#define SM_W3JT  10240                    // 640
#define SM_CUT   (SM_W3JT + 640)          // 64
#define SM_DIST  (SM_CUT + 64)            // 64
#define SM_SRC   (SM_DIST + 64)           // 64 (int)
#define SM_DST   (SM_SRC + 64)            // 64 (int)
#define SM_TOTALF (SM_DST + 64)           // 11136 floats
#define SMEM_BYTES (SM_TOTALF * 4)        // 44544 B

__global__ void __launch_bounds__(BLK, 3) conv_kernel(
    const float* __restrict__ pos,
    const int* __restrict__ src, const int* __restrict__ dst)
{
    extern __shared__ float smf[];
    float* Msm   = smf + SM_MSM;
    float* ysm   = smf + SM_YSM;
    float* w3jTs = smf + SM_W3JT;
    float* cutsm = smf + SM_CUT;
    float* distsm= smf + SM_DIST;
    int*   srcsm = (int*)(smf + SM_SRC);
    int*   dstsm = (int*)(smf + SM_DST);

    const int t  = threadIdx.x;
    const int u  = t & 31;       // lane == channel
    const int wr = t >> 5;       // warp 0..7 owns edges 8*wr .. 8*wr+7

    // stage w3jT table into smem (640 floats)
    #pragma unroll
    for (int r = 0; r < 3; ++r) {
        int idx = r * BLK + t;
        if (idx < 640) w3jTs[idx] = g_w3jT[idx];
    }

    // ================= Phase A: per-edge geometry (threads 0..63) ==========
    if (t < EPB) {
        int eg = blockIdx.x * EPB + t;
        float cut = 0.f, ux = 0.f, uy = 0.f, uz = 0.f, d = 0.f;
        int sn = 0, dn = 0;
        if (eg < N_EDGES) {
            sn = src[eg]; dn = dst[eg];
            float px = pos[3 * sn]     - pos[3 * dn];
            float py = pos[3 * sn + 1] - pos[3 * dn + 1];
            float pz = pos[3 * sn + 2] - pos[3 * dn + 2];
            d = sqrtf(px * px + py * py + pz * pz);
            float rin = 1.0f / fmaxf(d, 1e-12f);
            ux = px * rin; uy = py * rin; uz = pz * rin;
            if (d < 4.0f) cut = 1.0f;            // live-edge flag
        }
        cutsm[t] = cut;
        distsm[t] = d;
        srcsm[t] = sn; dstsm[t] = dn;
        const float s3 = 1.7320508075688772f, s15 = 3.872983346207417f;
        const float s5h = 1.118033988749895f, s15h = 1.9364916731037085f;
        float* ye = ysm + t * Y_PITCH;
        ye[0] = s3 * uy;
        ye[1] = s3 * uz;
        ye[2] = s3 * ux;
        ye[3] = s15 * ux * uy;
        ye[4] = s15 * uy * uz;
        ye[5] = s5h * (3.0f * uz * uz - 1.0f);
        ye[6] = s15 * ux * uz;
        ye[7] = s15h * (ux * ux - uy * uy);
        ye[8] = 1.0f;
        #pragma unroll
        for (int z = 9; z < Y_PITCH; ++z) ye[z] = 0.f;
    }
    __syncthreads();

    // ================= Phase D: per-edge M matrices ========================
    int   md_yoff[4], md_pos[4], md_row[4];
    #pragma unroll
    for (int g = 0; g < 4; ++g) {
        int idx = g * 32 + u;
        bool v = (idx < 115);
        int p = 10;
        if (v) { while (c_OFF[p] > idx) --p; } else { p = 0; }
        int r  = idx - c_OFF[p];
        int wk = 2 * c_PK[p] + 1;
        int a  = r / wk;
        int c  = r - a * wk;
        int jj = c_PJ[p];
        md_yoff[g] = (jj == 0) ? 8 : ((jj == 1) ? 0 : 3);
        md_pos[g]  = v ? (c_OFFP[p] + r) : 143;       // invalid -> pad slot
        md_row[g]  = idx * 5;
    }
    for (int q = 0; q < 8; ++q) {
        int e = 8 * wr + q;
        if (cutsm[e] == 0.f) continue;      // dead edge (warp-uniform)
        const float* ye = ysm + e * Y_PITCH;
        #pragma unroll
        for (int g = 0; g < 4; ++g) {
            const float* wrow = w3jTs + md_row[g];
            const float* yb = ye + md_yoff[g];
            float a = wrow[0] * yb[0];
            #pragma unroll
            for (int b = 1; b < 5; ++b) a = fmaf(wrow[b], yb[b], a);
            Msm[e * M_PITCH + md_pos[g]] = a;
        }
    }
    __syncwarp();

    // ================= Phase E: radial lookup + tensor product + scatter ===
    #pragma unroll
    for (int q = 0; q < 8; ++q) {
        int e = 8 * wr + q;
        if (cutsm[e] == 0.f) continue;      // warp-uniform skip
        int sn = srcsm[e], dn = dstsm[e];

        // radial*cutoff via interleaved fp16 table lerp (d < 4 guaranteed)
        float x = distsm[e] * ((float)RTAB_N * 0.25f);
        int i0 = (int)x;
        i0 = (i0 > RTAB_N - 1) ? (RTAB_N - 1) : i0;
        float f = x - (float)i0;
        const __half2* T = g_rtab_h + i0 * NRAD + u;
        float wv[NPATHS];
        #pragma unroll
        for (int p = 0; p < NPATHS; ++p) {
            float2 ab = __half22float2(T[p * 32]);
            wv[p] = fmaf(ab.y - ab.x, f, ab.x);
        }

        // coalesced channel-major node gather
        const float* xb = g_nodesT + (size_t)sn * FEAT;
        float x0r = xb[u];
        float x1r[3], x2r[5];
        #pragma unroll
        for (int a = 0; a < 3; ++a) x1r[a] = xb[32 + a * 32 + u];
        #pragma unroll
        for (int a = 0; a < 5; ++a) x2r[a] = xb[128 + a * 32 + u];

        const float4* M4 = reinterpret_cast<const float4*>(Msm + e * M_PITCH);
        float m0 = 0.f, m1[3] = {0.f, 0.f, 0.f}, m2[5] = {0.f, 0.f, 0.f, 0.f, 0.f};
        float s;

        {   // S1: floats 0..31 -> p0..p4
            float A[32];
            #pragma unroll
            for (int i = 0; i < 8; ++i)
                *reinterpret_cast<float4*>(&A[4 * i]) = M4[i];
            m0 = fmaf(wv[0], x0r * A[0], m0);
            #pragma unroll
            for (int c = 0; c < 3; ++c) m1[c] = fmaf(wv[1], x0r * A[4 + c], m1[c]);
            #pragma unroll
            for (int c = 0; c < 5; ++c) m2[c] = fmaf(wv[2], x0r * A[8 + c], m2[c]);
            #pragma unroll
            for (int c = 0; c < 3; ++c) {
                s = x1r[0] * A[16 + c] + x1r[1] * A[19 + c] + x1r[2] * A[22 + c];
                m1[c] = fmaf(wv[3], s, m1[c]);
            }
            s = x1r[0] * A[28] + x1r[1] * A[29] + x1r[2] * A[30];
            m0 = fmaf(wv[4], s, m0);
        }
        {   // S2: floats 32..59 -> p5, p6
            float A[28];
            #pragma unroll
            for (int i = 0; i < 7; ++i)
                *reinterpret_cast<float4*>(&A[4 * i]) = M4[8 + i];
            #pragma unroll
            for (int c = 0; c < 5; ++c) {
                s = x1r[0] * A[c] + x1r[1] * A[5 + c] + x1r[2] * A[10 + c];
                m2[c] = fmaf(wv[5], s, m2[c]);
            }
            #pragma unroll
            for (int c = 0; c < 3; ++c) {
                s = x1r[0] * A[16 + c] + x1r[1] * A[19 + c] + x1r[2] * A[22 + c];
                m1[c] = fmaf(wv[6], s, m1[c]);
            }
        }
        {   // S3: floats 60..87 -> p7 (2,0,2): A[a*5+c]
            float A[28];
            #pragma unroll
            for (int i = 0; i < 7; ++i)
                *reinterpret_cast<float4*>(&A[4 * i]) = M4[15 + i];
            #pragma unroll
            for (int c = 0; c < 5; ++c) {
                s = 0.f;
                #pragma unroll
                for (int a = 0; a < 5; ++a) s = fmaf(x2r[a], A[a * 5 + c], s);
                m2[c] = fmaf(wv[7], s, m2[c]);
            }
        }
        {   // S4: floats 88..111 -> p8 (A[a*3+c]), p9 (A[16+a])
            float A[24];
            #pragma unroll
            for (int i = 0; i < 6; ++i)
                *reinterpret_cast<float4*>(&A[4 * i]) = M4[22 + i];
            #pragma unroll
            for (int c = 0; c < 3; ++c) {
                s = 0.f;
                #pragma unroll
                for (int a = 0; a < 5; ++a) s = fmaf(x2r[a], A[a * 3 + c], s);
                m1[c] = fmaf(wv[8], s, m1[c]);
            }
            s = 0.f;
            #pragma unroll
            for (int a = 0; a < 5; ++a) s = fmaf(x2r[a], A[16 + a], s);
            m0 = fmaf(wv[9], s, m0);
        }
        {   // S5: floats 112..136 -> p10 (2,2,2): A[a*5+c]
            float A[28];
            #pragma unroll
            for (int i = 0; i < 7; ++i)
                *reinterpret_cast<float4*>(&A[4 * i]) = M4[28 + i];
            #pragma unroll
            for (int c = 0; c < 5; ++c) {
                s = 0.f;
                #pragma unroll
                for (int a = 0; a < 5; ++a) s = fmaf(x2r[a], A[a * 5 + c], s);
                m2[c] = fmaf(wv[10], s, m2[c]);
            }
        }

        // coalesced channel-major atomic scatter (9 x red.f32, no staging)
        float* ob = g_outT + (size_t)dn * FEAT;
        red1(&ob[u], m0);
        #pragma unroll
        for (int a = 0; a < 3; ++a) red1(&ob[32 + a * 32 + u], m1[a]);
        #pragma unroll
        for (int a = 0; a < 5; ++a) red1(&ob[128 + a * 32 + u], m2[a]);
    }
}

// ---------------------------------------------------------------------------
extern "C" void kernel_launch(void* const* d_in, const int* in_sizes, int n_in,
                              void* d_out, int out_size) {
    const float* nodes = (const float*)d_in[0];
    const float* pos   = (const float*)d_in[1];
    const int*   src   = (const int*)d_in[2];
    const int*   dst   = (const int*)d_in[3];
    const float* w1    = (const float*)d_in[4];
    const float* b1    = (const float*)d_in[5];
    const float* w2    = (const float*)d_in[6];
    const float* b2    = (const float*)d_in[7];
    float* out = (float*)d_out;

    setup_kernel<<<SETUP_BLOCKS, 256>>>(nodes, w1, b1, w2, b2);

    cudaFuncSetAttribute(conv_kernel,
                         cudaFuncAttributeMaxDynamicSharedMemorySize, SMEM_BYTES);
    int nblocks = (N_EDGES + EPB - 1) / EPB;
    conv_kernel<<<nblocks, BLK, SMEM_BYTES>>>(pos, src, dst);

    untranspose_kernel<<<2048, 256>>>(out);
}